// round 3
// baseline (speedup 1.0000x reference)
#include <cuda_runtime.h>
#include <cstddef>

#define NP 65536
#define NE 524288
#define RIGN 4096
#define NF 128
#define PITCH 129
#define DT_INV 60.0f

// ---------------- scratch (device globals; no allocation allowed) ----------------
__device__ float g_cent[6];
__device__ float g_pooled[NF];
__device__ float g_Rmat[9];
__device__ float g_tb[3];
__device__ float g_pe[(size_t)NP * NF];
__device__ float g_rel[(size_t)NE * NF];
__device__ float g_effA[(size_t)NP * NF];
__device__ float g_effB[(size_t)NP * NF];
__device__ float g_agg[(size_t)NP * NF];
// transposed weights, layout [K][128]
__device__ float g_peT0[15 * 128];
__device__ float g_peT1[128 * 128];
__device__ float g_reT0[31 * 128];
__device__ float g_reT1[128 * 128];
__device__ float g_reT2[128 * 128];
__device__ float g_rpT[384 * 128];
__device__ float g_ppT[256 * 128];
__device__ float g_flT0[128 * 128];
__device__ float g_flT1[128 * 128];

#define SMEM_BYTES ((2 * 128 * PITCH + 128 * 128) * 4)

// ---------------- helpers ----------------
__global__ void k_transpose(const float* __restrict__ src, float* __restrict__ dst, int K) {
    int idx = blockIdx.x * 256 + threadIdx.x;
    if (idx < K * 128) {
        int k = idx >> 7, f = idx & 127;
        dst[idx] = src[f * K + k];
    }
}

__global__ void k_centroid(const float* __restrict__ state) {
    __shared__ float red[256];
    float s[6] = {0, 0, 0, 0, 0, 0};
    for (int r = threadIdx.x; r < RIGN; r += 256) {
#pragma unroll
        for (int c = 0; c < 6; ++c) s[c] += state[r * 6 + c];
    }
#pragma unroll
    for (int c = 0; c < 6; ++c) {
        red[threadIdx.x] = s[c];
        __syncthreads();
        for (int off = 128; off > 0; off >>= 1) {
            if (threadIdx.x < off) red[threadIdx.x] += red[threadIdx.x + off];
            __syncthreads();
        }
        if (threadIdx.x == 0) g_cent[c] = red[0] * (1.0f / RIGN);
        __syncthreads();
    }
}

__device__ __forceinline__ void stage_w(float* sW, const float* __restrict__ g, int nelem) {
    for (int i = threadIdx.x; i < nelem; i += blockDim.x) sW[i] = g[i];
}

// load 128 contiguous rows of 128 floats (row-major) -> smem transposed pitch-129
__device__ __forceinline__ void stage_rows(float* sX, const float* __restrict__ g) {
    for (int i = threadIdx.x; i < 128 * 128; i += blockDim.x) {
        int r = i >> 7, k = i & 127;
        sX[k * PITCH + r] = g[i];
    }
}

__device__ __forceinline__ void init_bias(float acc[16][4], const float* __restrict__ b, int fg) {
    float b0 = b[fg], b1 = b[fg + 32], b2 = b[fg + 64], b3 = b[fg + 96];
#pragma unroll
    for (int i = 0; i < 16; ++i) { acc[i][0] = b0; acc[i][1] = b1; acc[i][2] = b2; acc[i][3] = b3; }
}

__device__ __forceinline__ void mlp_acc(const float* __restrict__ sX, const float* __restrict__ sW,
                                        int K, int fg, int rbase, float acc[16][4]) {
    for (int k = 0; k < K; ++k) {
        const float* wr = sW + k * 128 + fg;
        float w0 = wr[0], w1 = wr[32], w2 = wr[64], w3 = wr[96];
        const float* xr = sX + k * PITCH + rbase;
#pragma unroll
        for (int i = 0; i < 16; ++i) {
            float x = xr[i];
            acc[i][0] = fmaf(x, w0, acc[i][0]);
            acc[i][1] = fmaf(x, w1, acc[i][1]);
            acc[i][2] = fmaf(x, w2, acc[i][2]);
            acc[i][3] = fmaf(x, w3, acc[i][3]);
        }
    }
}

__device__ __forceinline__ void store_hT(float* sH, const float acc[16][4], int fg, int rbase) {
#pragma unroll
    for (int j = 0; j < 4; ++j) {
        float* d = sH + (fg + 32 * j) * PITCH + rbase;
#pragma unroll
        for (int i = 0; i < 16; ++i) d[i] = fmaxf(acc[i][j], 0.0f);
    }
}

// ---------------- particle encoder: [attr2, state](15) -> 128 -> 128 ----------------
__global__ void k_pe(const float* __restrict__ state, const float* __restrict__ attr,
                     const float* __restrict__ b0, const float* __restrict__ b1) {
    extern __shared__ float sm[];
    float* bufA = sm;
    float* bufB = sm + 128 * PITCH;
    float* sW = sm + 2 * 128 * PITCH;
    int t = threadIdx.x;
    int p0 = blockIdx.x * 128;
    if (t < 128) {
        int p = p0 + t;
        float a0 = attr[p * 3], a1 = attr[p * 3 + 1], a2 = attr[p * 3 + 2];
        float st[6], off[6];
#pragma unroll
        for (int c = 0; c < 6; ++c) st[c] = state[p * 6 + c];
        if (p < RIGN) {
#pragma unroll
            for (int c = 0; c < 6; ++c) off[c] = st[c] - g_cent[c];
        } else {
#pragma unroll
            for (int c = 0; c < 6; ++c) off[c] = 0.0f;
        }
        bufA[0 * PITCH + t] = a0; bufA[1 * PITCH + t] = a1; bufA[2 * PITCH + t] = a2;
#pragma unroll
        for (int c = 0; c < 6; ++c) bufA[(3 + c) * PITCH + t] = off[c];
#pragma unroll
        for (int c = 0; c < 6; ++c) bufA[(9 + c) * PITCH + t] = st[c];
    }
    stage_w(sW, g_peT0, 15 * 128);
    __syncthreads();
    int fg = t & 31, rbase = (t >> 5) * 16;
    float acc[16][4];
    init_bias(acc, b0, fg);
    mlp_acc(bufA, sW, 15, fg, rbase, acc);
    store_hT(bufB, acc, fg, rbase);
    __syncthreads();
    stage_w(sW, g_peT1, 128 * 128);
    __syncthreads();
    init_bias(acc, b1, fg);
    mlp_acc(bufB, sW, 128, fg, rbase, acc);
#pragma unroll
    for (int j = 0; j < 4; ++j)
#pragma unroll
        for (int i = 0; i < 16; ++i)
            g_pe[(size_t)(p0 + rbase + i) * 128 + fg + 32 * j] = fmaxf(acc[i][j], 0.0f);
}

// ---------------- relation encoder: 31 -> 128 -> 128 -> 128 ----------------
__global__ void k_rel(const float* __restrict__ state, const float* __restrict__ attr,
                      const float* __restrict__ Ra,
                      const int* __restrict__ recv, const int* __restrict__ send,
                      const float* __restrict__ b0, const float* __restrict__ b1,
                      const float* __restrict__ b2) {
    extern __shared__ float sm[];
    float* bufA = sm;
    float* bufB = sm + 128 * PITCH;
    float* sW = sm + 2 * 128 * PITCH;
    int t = threadIdx.x;
    int e0 = blockIdx.x * 128;
    if (t < 128) {
        int e = e0 + t;
        int rv = recv[e], sd = send[e];
        float cent[6];
#pragma unroll
        for (int c = 0; c < 6; ++c) cent[c] = g_cent[c];
        float str[6], sts[6];
#pragma unroll
        for (int c = 0; c < 6; ++c) str[c] = state[rv * 6 + c];
#pragma unroll
        for (int c = 0; c < 6; ++c) sts[c] = state[sd * 6 + c];
#pragma unroll
        for (int c = 0; c < 3; ++c) bufA[c * PITCH + t] = attr[rv * 3 + c];
#pragma unroll
        for (int c = 0; c < 6; ++c) bufA[(3 + c) * PITCH + t] = (rv < RIGN) ? (str[c] - cent[c]) : 0.0f;
#pragma unroll
        for (int c = 0; c < 3; ++c) bufA[(9 + c) * PITCH + t] = attr[sd * 3 + c];
#pragma unroll
        for (int c = 0; c < 6; ++c) bufA[(12 + c) * PITCH + t] = (sd < RIGN) ? (sts[c] - cent[c]) : 0.0f;
#pragma unroll
        for (int c = 0; c < 6; ++c) bufA[(18 + c) * PITCH + t] = str[c];
#pragma unroll
        for (int c = 0; c < 6; ++c) bufA[(24 + c) * PITCH + t] = sts[c];
        bufA[30 * PITCH + t] = Ra[e];
    }
    stage_w(sW, g_reT0, 31 * 128);
    __syncthreads();
    int fg = t & 31, rbase = (t >> 5) * 16;
    float acc[16][4];
    init_bias(acc, b0, fg);
    mlp_acc(bufA, sW, 31, fg, rbase, acc);
    store_hT(bufB, acc, fg, rbase);
    __syncthreads();
    stage_w(sW, g_reT1, 128 * 128);
    __syncthreads();
    init_bias(acc, b1, fg);
    mlp_acc(bufB, sW, 128, fg, rbase, acc);
    store_hT(bufA, acc, fg, rbase);
    __syncthreads();
    stage_w(sW, g_reT2, 128 * 128);
    __syncthreads();
    init_bias(acc, b2, fg);
    mlp_acc(bufA, sW, 128, fg, rbase, acc);
    float* dst = g_rel + (size_t)e0 * 128;
#pragma unroll
    for (int j = 0; j < 4; ++j)
#pragma unroll
        for (int i = 0; i < 16; ++i)
            dst[(rbase + i) * 128 + fg + 32 * j] = fmaxf(acc[i][j], 0.0f);
}

// ---------------- propagation edge pass: relu(rp_w @ [rel_enc, eff[recv], eff[send]]) -> scatter-add ----------------
__global__ void k_prop(const int* __restrict__ recv, const int* __restrict__ send,
                       const float* __restrict__ eff, const float* __restrict__ rp_b,
                       int use_eff) {
    extern __shared__ float sm[];
    float* bufA = sm;
    float* sW = sm + 2 * 128 * PITCH;
    int t = threadIdx.x;
    int e0 = blockIdx.x * 128;
    int fg = t & 31, rbase = (t >> 5) * 16;
    float acc[16][4];
    init_bias(acc, rp_b, fg);
    // chunk 0: relation_encode rows
    stage_rows(bufA, g_rel + (size_t)e0 * 128);
    stage_w(sW, g_rpT, 128 * 128);
    __syncthreads();
    mlp_acc(bufA, sW, 128, fg, rbase, acc);
    if (use_eff) {
        // chunk 1: eff[recv]
        __syncthreads();
        if (t < 128) {
            int rv = recv[e0 + t];
            const float4* s4 = (const float4*)(eff + (size_t)rv * 128);
#pragma unroll 8
            for (int k4 = 0; k4 < 32; ++k4) {
                float4 v = s4[k4];
                int k = 4 * k4;
                bufA[k * PITCH + t] = v.x;
                bufA[(k + 1) * PITCH + t] = v.y;
                bufA[(k + 2) * PITCH + t] = v.z;
                bufA[(k + 3) * PITCH + t] = v.w;
            }
        }
        stage_w(sW, g_rpT + 128 * 128, 128 * 128);
        __syncthreads();
        mlp_acc(bufA, sW, 128, fg, rbase, acc);
        // chunk 2: eff[send]
        __syncthreads();
        if (t < 128) {
            int sd = send[e0 + t];
            const float4* s4 = (const float4*)(eff + (size_t)sd * 128);
#pragma unroll 8
            for (int k4 = 0; k4 < 32; ++k4) {
                float4 v = s4[k4];
                int k = 4 * k4;
                bufA[k * PITCH + t] = v.x;
                bufA[(k + 1) * PITCH + t] = v.y;
                bufA[(k + 2) * PITCH + t] = v.z;
                bufA[(k + 3) * PITCH + t] = v.w;
            }
        }
        stage_w(sW, g_rpT + 2 * 128 * 128, 128 * 128);
        __syncthreads();
        mlp_acc(bufA, sW, 128, fg, rbase, acc);
    }
    // scatter-add relu(rel_eff) into agg[recv]
#pragma unroll
    for (int i = 0; i < 16; ++i) {
        int e = e0 + rbase + i;
        int rv = recv[e];
        float* dst = g_agg + (size_t)rv * 128 + fg;
        atomicAdd(dst, fmaxf(acc[i][0], 0.0f));
        atomicAdd(dst + 32, fmaxf(acc[i][1], 0.0f));
        atomicAdd(dst + 64, fmaxf(acc[i][2], 0.0f));
        atomicAdd(dst + 96, fmaxf(acc[i][3], 0.0f));
    }
}

// ---------------- particle update: relu(pp_w @ [pe, agg]) ----------------
__global__ void k_pupdate(const float* __restrict__ pp_b, float* __restrict__ eff_out) {
    extern __shared__ float sm[];
    float* bufA = sm;
    float* sW = sm + 2 * 128 * PITCH;
    int t = threadIdx.x;
    int p0 = blockIdx.x * 128;
    int fg = t & 31, rbase = (t >> 5) * 16;
    float acc[16][4];
    init_bias(acc, pp_b, fg);
    stage_rows(bufA, g_pe + (size_t)p0 * 128);
    stage_w(sW, g_ppT, 128 * 128);
    __syncthreads();
    mlp_acc(bufA, sW, 128, fg, rbase, acc);
    __syncthreads();
    stage_rows(bufA, g_agg + (size_t)p0 * 128);
    stage_w(sW, g_ppT + 128 * 128, 128 * 128);
    __syncthreads();
    mlp_acc(bufA, sW, 128, fg, rbase, acc);
#pragma unroll
    for (int j = 0; j < 4; ++j)
#pragma unroll
        for (int i = 0; i < 16; ++i)
            eff_out[(size_t)(p0 + rbase + i) * 128 + fg + 32 * j] = fmaxf(acc[i][j], 0.0f);
}

// ---------------- rigid pooling + small MLP + rigid output ----------------
__global__ void k_pool(const float* __restrict__ eff) {
    int f = threadIdx.x;  // 128
    int r0 = blockIdx.x * 128;
    float s = 0.0f;
    for (int r = 0; r < 128; ++r) s += eff[(size_t)(r0 + r) * 128 + f];
    atomicAdd(&g_pooled[f], s);
}

__global__ void k_rigid_mlp(const float* __restrict__ w0, const float* __restrict__ b0,
                            const float* __restrict__ w1, const float* __restrict__ b1,
                            const float* __restrict__ w2, const float* __restrict__ b2) {
    __shared__ float pin[128], h0[128], h1[128], tt[7];
    int t = threadIdx.x;  // 128
    pin[t] = g_pooled[t] * (1.0f / RIGN);
    __syncthreads();
    float s = b0[t];
    for (int k = 0; k < 128; ++k) s = fmaf(w0[t * 128 + k], pin[k], s);
    h0[t] = fmaxf(s, 0.0f);
    __syncthreads();
    s = b1[t];
    for (int k = 0; k < 128; ++k) s = fmaf(w1[t * 128 + k], h0[k], s);
    h1[t] = fmaxf(s, 0.0f);
    __syncthreads();
    if (t < 7) {
        s = b2[t];
        for (int k = 0; k < 128; ++k) s = fmaf(w2[t * 128 + k], h1[k], s);
        tt[t] = s;
    }
    __syncthreads();
    if (t == 0) {
        float qw = tt[0], qx = tt[1], qy = tt[2], qz = tt[3];
        float inv = rsqrtf(qw * qw + qx * qx + qy * qy + qz * qz);
        qw *= inv; qx *= inv; qy *= inv; qz *= inv;
        g_Rmat[0] = 1.0f - 2.0f * (qy * qy + qz * qz);
        g_Rmat[1] = 2.0f * (qx * qy + qz * qw);
        g_Rmat[2] = 2.0f * (qx * qz - qy * qw);
        g_Rmat[3] = 2.0f * (qx * qy - qz * qw);
        g_Rmat[4] = 1.0f - 2.0f * (qx * qx + qz * qz);
        g_Rmat[5] = 2.0f * (qy * qz + qx * qw);
        g_Rmat[6] = 2.0f * (qx * qz + qy * qw);
        g_Rmat[7] = 2.0f * (qy * qz - qx * qw);
        g_Rmat[8] = 1.0f - 2.0f * (qx * qx + qy * qy);
        g_tb[0] = tt[4]; g_tb[1] = tt[5]; g_tb[2] = tt[6];
    }
}

__global__ void k_rigid_out(const float* __restrict__ state, float* __restrict__ out) {
    int i = blockIdx.x * 256 + threadIdx.x;
    if (i >= RIGN) return;
    float c0 = g_cent[0], c1 = g_cent[1], c2 = g_cent[2];
    float p0x = state[i * 6], p0y = state[i * 6 + 1], p0z = state[i * 6 + 2];
    float dx = p0x - c0, dy = p0y - c1, dz = p0z - c2;
    float p1x = dx * g_Rmat[0] + dy * g_Rmat[3] + dz * g_Rmat[6] + g_tb[0] + c0;
    float p1y = dx * g_Rmat[1] + dy * g_Rmat[4] + dz * g_Rmat[7] + g_tb[1] + c1;
    float p1z = dx * g_Rmat[2] + dy * g_Rmat[5] + dz * g_Rmat[8] + g_tb[2] + c2;
    out[i * 3] = (p1x - p0x) * DT_INV;
    out[i * 3 + 1] = (p1y - p0y) * DT_INV;
    out[i * 3 + 2] = (p1z - p0z) * DT_INV;
}

// ---------------- fluid predictor: 128 -> 128 -> 128 -> 3 ----------------
__global__ void k_fluid(const float* __restrict__ eff, const float* __restrict__ fb0,
                        const float* __restrict__ fb1, const float* __restrict__ fw2,
                        const float* __restrict__ fb2, float* __restrict__ out) {
    extern __shared__ float sm[];
    float* bufA = sm;
    float* bufB = sm + 128 * PITCH;
    float* sW = sm + 2 * 128 * PITCH;
    int t = threadIdx.x;
    int p0 = RIGN + blockIdx.x * 128;
    int fg = t & 31, rbase = (t >> 5) * 16;
    float acc[16][4];
    stage_rows(bufA, eff + (size_t)p0 * 128);
    stage_w(sW, g_flT0, 128 * 128);
    __syncthreads();
    init_bias(acc, fb0, fg);
    mlp_acc(bufA, sW, 128, fg, rbase, acc);
    store_hT(bufB, acc, fg, rbase);
    __syncthreads();
    stage_w(sW, g_flT1, 128 * 128);
    __syncthreads();
    init_bias(acc, fb1, fg);
    mlp_acc(bufB, sW, 128, fg, rbase, acc);
    store_hT(bufA, acc, fg, rbase);
    __syncthreads();
    if (t < 128) {
        float o0 = fb2[0], o1 = fb2[1], o2 = fb2[2];
        for (int k = 0; k < 128; ++k) {
            float x = bufA[k * PITCH + t];
            o0 = fmaf(fw2[k], x, o0);
            o1 = fmaf(fw2[128 + k], x, o1);
            o2 = fmaf(fw2[256 + k], x, o2);
        }
        size_t base = (size_t)(p0 + t) * 3;
        out[base] = o0; out[base + 1] = o1; out[base + 2] = o2;
    }
}

// ---------------- launch ----------------
extern "C" void kernel_launch(void* const* d_in, const int* in_sizes, int n_in,
                              void* d_out, int out_size) {
    const float* state = (const float*)d_in[0];
    const float* attr = (const float*)d_in[1];
    const float* Ra = (const float*)d_in[2];
    const int* recv = (const int*)d_in[3];
    const int* send = (const int*)d_in[4];
    const float* pe_w0 = (const float*)d_in[5];
    const float* pe_b0 = (const float*)d_in[6];
    const float* pe_w1 = (const float*)d_in[7];
    const float* pe_b1 = (const float*)d_in[8];
    const float* re_w0 = (const float*)d_in[9];
    const float* re_b0 = (const float*)d_in[10];
    const float* re_w1 = (const float*)d_in[11];
    const float* re_b1 = (const float*)d_in[12];
    const float* re_w2 = (const float*)d_in[13];
    const float* re_b2 = (const float*)d_in[14];
    const float* rp_w = (const float*)d_in[15];
    const float* rp_b = (const float*)d_in[16];
    const float* pp_w = (const float*)d_in[17];
    const float* pp_b = (const float*)d_in[18];
    const float* rg_w0 = (const float*)d_in[19];
    const float* rg_b0 = (const float*)d_in[20];
    const float* rg_w1 = (const float*)d_in[21];
    const float* rg_b1 = (const float*)d_in[22];
    const float* rg_w2 = (const float*)d_in[23];
    const float* rg_b2 = (const float*)d_in[24];
    const float* fl_w0 = (const float*)d_in[25];
    const float* fl_b0 = (const float*)d_in[26];
    const float* fl_w1 = (const float*)d_in[27];
    const float* fl_b1 = (const float*)d_in[28];
    const float* fl_w2 = (const float*)d_in[29];
    const float* fl_b2 = (const float*)d_in[30];
    float* out = (float*)d_out;

    cudaFuncSetAttribute(k_pe, cudaFuncAttributeMaxDynamicSharedMemorySize, SMEM_BYTES);
    cudaFuncSetAttribute(k_rel, cudaFuncAttributeMaxDynamicSharedMemorySize, SMEM_BYTES);
    cudaFuncSetAttribute(k_prop, cudaFuncAttributeMaxDynamicSharedMemorySize, SMEM_BYTES);
    cudaFuncSetAttribute(k_pupdate, cudaFuncAttributeMaxDynamicSharedMemorySize, SMEM_BYTES);
    cudaFuncSetAttribute(k_fluid, cudaFuncAttributeMaxDynamicSharedMemorySize, SMEM_BYTES);

    float *peT0p, *peT1p, *reT0p, *reT1p, *reT2p, *rpTp, *ppTp, *flT0p, *flT1p;
    float *aggp, *pooledp, *effAp, *effBp;
    cudaGetSymbolAddress((void**)&peT0p, g_peT0);
    cudaGetSymbolAddress((void**)&peT1p, g_peT1);
    cudaGetSymbolAddress((void**)&reT0p, g_reT0);
    cudaGetSymbolAddress((void**)&reT1p, g_reT1);
    cudaGetSymbolAddress((void**)&reT2p, g_reT2);
    cudaGetSymbolAddress((void**)&rpTp, g_rpT);
    cudaGetSymbolAddress((void**)&ppTp, g_ppT);
    cudaGetSymbolAddress((void**)&flT0p, g_flT0);
    cudaGetSymbolAddress((void**)&flT1p, g_flT1);
    cudaGetSymbolAddress((void**)&aggp, g_agg);
    cudaGetSymbolAddress((void**)&pooledp, g_pooled);
    cudaGetSymbolAddress((void**)&effAp, g_effA);
    cudaGetSymbolAddress((void**)&effBp, g_effB);

    // setup: transpose weights to [K][128]
    k_transpose<<<(15 * 128 + 255) / 256, 256>>>(pe_w0, peT0p, 15);
    k_transpose<<<(128 * 128 + 255) / 256, 256>>>(pe_w1, peT1p, 128);
    k_transpose<<<(31 * 128 + 255) / 256, 256>>>(re_w0, reT0p, 31);
    k_transpose<<<(128 * 128 + 255) / 256, 256>>>(re_w1, reT1p, 128);
    k_transpose<<<(128 * 128 + 255) / 256, 256>>>(re_w2, reT2p, 128);
    k_transpose<<<(384 * 128 + 255) / 256, 256>>>(rp_w, rpTp, 384);
    k_transpose<<<(256 * 128 + 255) / 256, 256>>>(pp_w, ppTp, 256);
    k_transpose<<<(128 * 128 + 255) / 256, 256>>>(fl_w0, flT0p, 128);
    k_transpose<<<(128 * 128 + 255) / 256, 256>>>(fl_w1, flT1p, 128);

    k_centroid<<<1, 256>>>(state);
    k_pe<<<NP / 128, 256, SMEM_BYTES>>>(state, attr, pe_b0, pe_b1);
    k_rel<<<NE / 128, 256, SMEM_BYTES>>>(state, attr, Ra, recv, send, re_b0, re_b1, re_b2);

    // propagation step 1 (effect == 0 -> skip eff chunks)
    cudaMemsetAsync(aggp, 0, (size_t)NP * NF * sizeof(float));
    k_prop<<<NE / 128, 256, SMEM_BYTES>>>(recv, send, effAp, rp_b, 0);
    k_pupdate<<<NP / 128, 256, SMEM_BYTES>>>(pp_b, effAp);

    // propagation step 2
    cudaMemsetAsync(aggp, 0, (size_t)NP * NF * sizeof(float));
    k_prop<<<NE / 128, 256, SMEM_BYTES>>>(recv, send, effAp, rp_b, 1);
    k_pupdate<<<NP / 128, 256, SMEM_BYTES>>>(pp_b, effBp);

    // rigid branch
    cudaMemsetAsync(pooledp, 0, NF * sizeof(float));
    k_pool<<<RIGN / 128, 128>>>(effBp);
    k_rigid_mlp<<<1, 128>>>(rg_w0, rg_b0, rg_w1, rg_b1, rg_w2, rg_b2);
    k_rigid_out<<<RIGN / 256, 256>>>(state, out);

    // fluid branch
    k_fluid<<<(NP - RIGN) / 128, 256, SMEM_BYTES>>>(effBp, fl_b0, fl_b1, fl_w2, fl_b2, out);
}

// round 6
// speedup vs baseline: 1.4619x; 1.4619x over previous
#include <cuda_runtime.h>
#include <cstddef>

#define NP 65536
#define NE 524288
#define RIGN 4096
#define NF 128
#define PITCH 130
#define NT 512
#define DT_INV 60.0f

typedef unsigned long long ull;

// ---------------- scratch (device globals; no allocation allowed) ----------------
__device__ float g_cent[6];
__device__ float g_pooled[NF];
__device__ float g_Rmat[9];
__device__ float g_tb[3];
__device__ float g_pe[(size_t)NP * NF];
__device__ float g_rel[(size_t)NE * NF];
__device__ float g_effA[(size_t)NP * NF];
__device__ float g_effB[(size_t)NP * NF];
__device__ float g_agg[(size_t)NP * NF];
// transposed weights, layout [K][128]
__device__ float g_peT0[15 * 128];
__device__ float g_peT1[128 * 128];
__device__ float g_reT0[31 * 128];
__device__ float g_reT1[128 * 128];
__device__ float g_reT2[128 * 128];
__device__ float g_rpT[384 * 128];
__device__ float g_ppT[256 * 128];
__device__ float g_flT0[128 * 128];
__device__ float g_flT1[128 * 128];

#define SMEM_BYTES ((2 * 128 * PITCH + 128 * 128) * 4)

// ---------------- f32x2 helpers ----------------
__device__ __forceinline__ ull ffma2(ull a, ull b, ull c) {
    ull d;
    asm("fma.rn.f32x2 %0, %1, %2, %3;" : "=l"(d) : "l"(a), "l"(b), "l"(c));
    return d;
}
__device__ __forceinline__ ull pack2(float lo, float hi) {
    ull r;
    asm("mov.b64 %0, {%1, %2};" : "=l"(r) : "f"(lo), "f"(hi));
    return r;
}
__device__ __forceinline__ float2 unpack2(ull v) {
    float2 f;
    asm("mov.b64 {%0, %1}, %2;" : "=f"(f.x), "=f"(f.y) : "l"(v));
    return f;
}

// ---------------- setup kernels ----------------
__global__ void k_transpose_all(const float* __restrict__ pe_w0, const float* __restrict__ pe_w1,
                                const float* __restrict__ re_w0, const float* __restrict__ re_w1,
                                const float* __restrict__ re_w2, const float* __restrict__ rp_w,
                                const float* __restrict__ pp_w, const float* __restrict__ fl_w0,
                                const float* __restrict__ fl_w1) {
    int b = blockIdx.x;
    const float* src;
    float* dst;
    int K, base;
    if (b < 8)        { src = pe_w0; dst = g_peT0; K = 15;  base = 0; }
    else if (b < 72)  { src = pe_w1; dst = g_peT1; K = 128; base = 8; }
    else if (b < 88)  { src = re_w0; dst = g_reT0; K = 31;  base = 72; }
    else if (b < 152) { src = re_w1; dst = g_reT1; K = 128; base = 88; }
    else if (b < 216) { src = re_w2; dst = g_reT2; K = 128; base = 152; }
    else if (b < 408) { src = rp_w;  dst = g_rpT;  K = 384; base = 216; }
    else if (b < 536) { src = pp_w;  dst = g_ppT;  K = 256; base = 408; }
    else if (b < 600) { src = fl_w0; dst = g_flT0; K = 128; base = 536; }
    else              { src = fl_w1; dst = g_flT1; K = 128; base = 600; }
    int idx = (b - base) * 256 + threadIdx.x;
    if (idx < K * 128) {
        int k = idx >> 7, f = idx & 127;
        dst[idx] = src[f * K + k];
    }
}

__global__ void k_centroid(const float* __restrict__ state) {
    __shared__ float red[256];
    float s[6] = {0, 0, 0, 0, 0, 0};
    for (int r = threadIdx.x; r < RIGN; r += 256) {
#pragma unroll
        for (int c = 0; c < 6; ++c) s[c] += state[r * 6 + c];
    }
#pragma unroll
    for (int c = 0; c < 6; ++c) {
        red[threadIdx.x] = s[c];
        __syncthreads();
        for (int off = 128; off > 0; off >>= 1) {
            if (threadIdx.x < off) red[threadIdx.x] += red[threadIdx.x + off];
            __syncthreads();
        }
        if (threadIdx.x == 0) g_cent[c] = red[0] * (1.0f / RIGN);
        __syncthreads();
    }
}

// ---------------- shared helpers ----------------
__device__ __forceinline__ void stage_w(float* sW, const float* __restrict__ g, int nelem) {
    int n4 = nelem >> 2;
    const float4* g4 = (const float4*)g;
    float4* s4 = (float4*)sW;
    for (int i = threadIdx.x; i < n4; i += NT) s4[i] = g4[i];
}

// load 128 contiguous rows of 128 floats (row-major) -> smem transposed pitch-130
__device__ __forceinline__ void stage_rows(float* sX, const float* __restrict__ g) {
    for (int i = threadIdx.x; i < 128 * 128; i += NT) {
        int r = i >> 7, k = i & 127;
        sX[k * PITCH + r] = g[i];
    }
}

__device__ __forceinline__ void init_bias2(ull acc[4][4], const float* __restrict__ b, int fg) {
#pragma unroll
    for (int j = 0; j < 4; ++j) {
        float bj = b[fg + 32 * j];
        ull bp = pack2(bj, bj);
#pragma unroll
        for (int p = 0; p < 4; ++p) acc[p][j] = bp;
    }
}

// core GEMM tile: 128 rows x 128 feats, each thread 8 rows (as 4 pairs) x 4 feats
__device__ __forceinline__ void mlp_acc2(const float* sX, const float* sW, int K,
                                         int fg, int rbase, ull acc[4][4]) {
    for (int k = 0; k < K; ++k) {
        const float* wr = sW + k * 128 + fg;
        ull w0 = pack2(wr[0], wr[0]);
        ull w1 = pack2(wr[32], wr[32]);
        ull w2 = pack2(wr[64], wr[64]);
        ull w3 = pack2(wr[96], wr[96]);
        const ull* xr = (const ull*)(sX + k * PITCH + rbase);
#pragma unroll
        for (int p = 0; p < 4; ++p) {
            ull x = xr[p];
            acc[p][0] = ffma2(x, w0, acc[p][0]);
            acc[p][1] = ffma2(x, w1, acc[p][1]);
            acc[p][2] = ffma2(x, w2, acc[p][2]);
            acc[p][3] = ffma2(x, w3, acc[p][3]);
        }
    }
}

// relu + store hidden activations back to smem (transposed), 64-bit stores
__device__ __forceinline__ void store_hT2(float* sH, const ull acc[4][4], int fg, int rbase) {
#pragma unroll
    for (int j = 0; j < 4; ++j) {
        ull* d = (ull*)(sH + (fg + 32 * j) * PITCH + rbase);
#pragma unroll
        for (int p = 0; p < 4; ++p) {
            float2 v = unpack2(acc[p][j]);
            d[p] = pack2(fmaxf(v.x, 0.0f), fmaxf(v.y, 0.0f));
        }
    }
}

// relu + store to global row-major [row][128]
__device__ __forceinline__ void store_gout(float* __restrict__ g, const ull acc[4][4],
                                           int fg, int rbase, int p0) {
#pragma unroll
    for (int p = 0; p < 4; ++p) {
#pragma unroll
        for (int j = 0; j < 4; ++j) {
            float2 v = unpack2(acc[p][j]);
            g[(size_t)(p0 + rbase + 2 * p) * 128 + fg + 32 * j] = fmaxf(v.x, 0.0f);
            g[(size_t)(p0 + rbase + 2 * p + 1) * 128 + fg + 32 * j] = fmaxf(v.y, 0.0f);
        }
    }
}

// ---------------- particle encoder: [attr2, state](15) -> 128 -> 128 ----------------
__global__ void __launch_bounds__(NT) k_pe(const float* __restrict__ state,
                                           const float* __restrict__ attr,
                                           const float* __restrict__ b0,
                                           const float* __restrict__ b1) {
    extern __shared__ float sm[];
    float* bufA = sm;
    float* bufB = sm + 128 * PITCH;
    float* sW = sm + 2 * 128 * PITCH;
    int t = threadIdx.x;
    int p0 = blockIdx.x * 128;
    int row = t & 127, grp = t >> 7;
    {
        int p = p0 + row;
        if (grp == 0) {
            bufA[0 * PITCH + row] = attr[p * 3];
            bufA[1 * PITCH + row] = attr[p * 3 + 1];
            bufA[2 * PITCH + row] = attr[p * 3 + 2];
        } else if (grp == 1) {
#pragma unroll
            for (int c = 0; c < 6; ++c) {
                float s = state[p * 6 + c];
                bufA[(3 + c) * PITCH + row] = (p < RIGN) ? (s - g_cent[c]) : 0.0f;
            }
        } else if (grp == 2) {
#pragma unroll
            for (int c = 0; c < 6; ++c) bufA[(9 + c) * PITCH + row] = state[p * 6 + c];
        }
    }
    stage_w(sW, g_peT0, 15 * 128);
    __syncthreads();
    int fg = t & 31, rbase = (t >> 5) * 8;
    ull acc[4][4];
    init_bias2(acc, b0, fg);
    mlp_acc2(bufA, sW, 15, fg, rbase, acc);
    store_hT2(bufB, acc, fg, rbase);
    __syncthreads();
    stage_w(sW, g_peT1, 128 * 128);
    __syncthreads();
    init_bias2(acc, b1, fg);
    mlp_acc2(bufB, sW, 128, fg, rbase, acc);
    store_gout(g_pe, acc, fg, rbase, p0);
}

// ---------------- relation encoder: 31 -> 128 -> 128 -> 128 ----------------
__global__ void __launch_bounds__(NT) k_rel(const float* __restrict__ state,
                                            const float* __restrict__ attr,
                                            const float* __restrict__ Ra,
                                            const int* __restrict__ recv,
                                            const int* __restrict__ send,
                                            const float* __restrict__ b0,
                                            const float* __restrict__ b1,
                                            const float* __restrict__ b2) {
    extern __shared__ float sm[];
    float* bufA = sm;
    float* bufB = sm + 128 * PITCH;
    float* sW = sm + 2 * 128 * PITCH;
    int t = threadIdx.x;
    int e0 = blockIdx.x * 128;
    int row = t & 127, grp = t >> 7;
    {
        int e = e0 + row;
        if (grp == 0) {           // recv attr + recv offset
            int rv = recv[e];
#pragma unroll
            for (int c = 0; c < 3; ++c) bufA[c * PITCH + row] = attr[rv * 3 + c];
#pragma unroll
            for (int c = 0; c < 6; ++c) {
                float s = state[rv * 6 + c];
                bufA[(3 + c) * PITCH + row] = (rv < RIGN) ? (s - g_cent[c]) : 0.0f;
            }
        } else if (grp == 1) {    // send attr + send offset
            int sd = send[e];
#pragma unroll
            for (int c = 0; c < 3; ++c) bufA[(9 + c) * PITCH + row] = attr[sd * 3 + c];
#pragma unroll
            for (int c = 0; c < 6; ++c) {
                float s = state[sd * 6 + c];
                bufA[(12 + c) * PITCH + row] = (sd < RIGN) ? (s - g_cent[c]) : 0.0f;
            }
        } else if (grp == 2) {    // recv state
            int rv = recv[e];
#pragma unroll
            for (int c = 0; c < 6; ++c) bufA[(18 + c) * PITCH + row] = state[rv * 6 + c];
        } else {                  // send state + Ra
            int sd = send[e];
#pragma unroll
            for (int c = 0; c < 6; ++c) bufA[(24 + c) * PITCH + row] = state[sd * 6 + c];
            bufA[30 * PITCH + row] = Ra[e];
        }
    }
    stage_w(sW, g_reT0, 31 * 128);
    __syncthreads();
    int fg = t & 31, rbase = (t >> 5) * 8;
    ull acc[4][4];
    init_bias2(acc, b0, fg);
    mlp_acc2(bufA, sW, 31, fg, rbase, acc);
    store_hT2(bufB, acc, fg, rbase);
    __syncthreads();
    stage_w(sW, g_reT1, 128 * 128);
    __syncthreads();
    init_bias2(acc, b1, fg);
    mlp_acc2(bufB, sW, 128, fg, rbase, acc);
    store_hT2(bufA, acc, fg, rbase);
    __syncthreads();
    stage_w(sW, g_reT2, 128 * 128);
    __syncthreads();
    init_bias2(acc, b2, fg);
    mlp_acc2(bufA, sW, 128, fg, rbase, acc);
    store_gout(g_rel, acc, fg, rbase, e0);
}

// gather 128 rows of effect[idx[e]] -> smem transposed; all NT threads participate
__device__ __forceinline__ void stage_gather(float* sX, const float* __restrict__ eff,
                                             const int* __restrict__ idx, int e0) {
    int t = threadIdx.x;
    int row = t & 127, kq = t >> 7;  // kq in 0..3, each covers 32 k
    int v = idx[e0 + row];
    const float4* s4 = (const float4*)(eff + (size_t)v * 128 + kq * 32);
#pragma unroll
    for (int k4 = 0; k4 < 8; ++k4) {
        float4 w = s4[k4];
        int k = kq * 32 + 4 * k4;
        sX[k * PITCH + row] = w.x;
        sX[(k + 1) * PITCH + row] = w.y;
        sX[(k + 2) * PITCH + row] = w.z;
        sX[(k + 3) * PITCH + row] = w.w;
    }
}

// ---------------- propagation edge pass ----------------
__global__ void __launch_bounds__(NT) k_prop(const int* __restrict__ recv,
                                             const int* __restrict__ send,
                                             const float* __restrict__ eff,
                                             const float* __restrict__ rp_b, int use_eff) {
    extern __shared__ float sm[];
    float* bufA = sm;
    float* sW = sm + 2 * 128 * PITCH;
    int t = threadIdx.x;
    int e0 = blockIdx.x * 128;
    int fg = t & 31, rbase = (t >> 5) * 8;
    ull acc[4][4];
    init_bias2(acc, rp_b, fg);
    // chunk 0: relation_encode rows
    stage_rows(bufA, g_rel + (size_t)e0 * 128);
    stage_w(sW, g_rpT, 128 * 128);
    __syncthreads();
    mlp_acc2(bufA, sW, 128, fg, rbase, acc);
    if (use_eff) {
        // chunk 1: eff[recv]
        __syncthreads();
        stage_gather(bufA, eff, recv, e0);
        stage_w(sW, g_rpT + 128 * 128, 128 * 128);
        __syncthreads();
        mlp_acc2(bufA, sW, 128, fg, rbase, acc);
        // chunk 2: eff[send]
        __syncthreads();
        stage_gather(bufA, eff, send, e0);
        stage_w(sW, g_rpT + 2 * 128 * 128, 128 * 128);
        __syncthreads();
        mlp_acc2(bufA, sW, 128, fg, rbase, acc);
    }
    // scatter-add relu(rel_eff) into agg[recv]
#pragma unroll
    for (int p = 0; p < 4; ++p) {
        int e = e0 + rbase + 2 * p;
        int rv0 = recv[e], rv1 = recv[e + 1];
        float* d0 = g_agg + (size_t)rv0 * 128 + fg;
        float* d1 = g_agg + (size_t)rv1 * 128 + fg;
#pragma unroll
        for (int j = 0; j < 4; ++j) {
            float2 v = unpack2(acc[p][j]);
            atomicAdd(d0 + 32 * j, fmaxf(v.x, 0.0f));
            atomicAdd(d1 + 32 * j, fmaxf(v.y, 0.0f));
        }
    }
}

// ---------------- particle update: relu(pp_w @ [pe, agg]) ----------------
__global__ void __launch_bounds__(NT) k_pupdate(const float* __restrict__ pp_b,
                                                float* __restrict__ eff_out) {
    extern __shared__ float sm[];
    float* bufA = sm;
    float* sW = sm + 2 * 128 * PITCH;
    int t = threadIdx.x;
    int p0 = blockIdx.x * 128;
    int fg = t & 31, rbase = (t >> 5) * 8;
    ull acc[4][4];
    init_bias2(acc, pp_b, fg);
    stage_rows(bufA, g_pe + (size_t)p0 * 128);
    stage_w(sW, g_ppT, 128 * 128);
    __syncthreads();
    mlp_acc2(bufA, sW, 128, fg, rbase, acc);
    __syncthreads();
    stage_rows(bufA, g_agg + (size_t)p0 * 128);
    stage_w(sW, g_ppT + 128 * 128, 128 * 128);
    __syncthreads();
    mlp_acc2(bufA, sW, 128, fg, rbase, acc);
    store_gout(eff_out, acc, fg, rbase, p0);
}

// ---------------- rigid pooling + small MLP + rigid output ----------------
__global__ void k_pool(const float* __restrict__ eff) {
    int f = threadIdx.x;  // 128
    int r0 = blockIdx.x * 128;
    float s = 0.0f;
    for (int r = 0; r < 128; ++r) s += eff[(size_t)(r0 + r) * 128 + f];
    atomicAdd(&g_pooled[f], s);
}

__global__ void k_rigid_mlp(const float* __restrict__ w0, const float* __restrict__ b0,
                            const float* __restrict__ w1, const float* __restrict__ b1,
                            const float* __restrict__ w2, const float* __restrict__ b2) {
    __shared__ float pin[128], h0[128], h1[128], tt[7];
    int t = threadIdx.x;  // 128
    pin[t] = g_pooled[t] * (1.0f / RIGN);
    __syncthreads();
    float s = b0[t];
    for (int k = 0; k < 128; ++k) s = fmaf(w0[t * 128 + k], pin[k], s);
    h0[t] = fmaxf(s, 0.0f);
    __syncthreads();
    s = b1[t];
    for (int k = 0; k < 128; ++k) s = fmaf(w1[t * 128 + k], h0[k], s);
    h1[t] = fmaxf(s, 0.0f);
    __syncthreads();
    if (t < 7) {
        s = b2[t];
        for (int k = 0; k < 128; ++k) s = fmaf(w2[t * 128 + k], h1[k], s);
        tt[t] = s;
    }
    __syncthreads();
    if (t == 0) {
        float qw = tt[0], qx = tt[1], qy = tt[2], qz = tt[3];
        float inv = rsqrtf(qw * qw + qx * qx + qy * qy + qz * qz);
        qw *= inv; qx *= inv; qy *= inv; qz *= inv;
        g_Rmat[0] = 1.0f - 2.0f * (qy * qy + qz * qz);
        g_Rmat[1] = 2.0f * (qx * qy + qz * qw);
        g_Rmat[2] = 2.0f * (qx * qz - qy * qw);
        g_Rmat[3] = 2.0f * (qx * qy - qz * qw);
        g_Rmat[4] = 1.0f - 2.0f * (qx * qx + qz * qz);
        g_Rmat[5] = 2.0f * (qy * qz + qx * qw);
        g_Rmat[6] = 2.0f * (qx * qz + qy * qw);
        g_Rmat[7] = 2.0f * (qy * qz - qx * qw);
        g_Rmat[8] = 1.0f - 2.0f * (qx * qx + qy * qy);
        g_tb[0] = tt[4]; g_tb[1] = tt[5]; g_tb[2] = tt[6];
    }
}

__global__ void k_rigid_out(const float* __restrict__ state, float* __restrict__ out) {
    int i = blockIdx.x * 256 + threadIdx.x;
    if (i >= RIGN) return;
    float c0 = g_cent[0], c1 = g_cent[1], c2 = g_cent[2];
    float p0x = state[i * 6], p0y = state[i * 6 + 1], p0z = state[i * 6 + 2];
    float dx = p0x - c0, dy = p0y - c1, dz = p0z - c2;
    float p1x = dx * g_Rmat[0] + dy * g_Rmat[3] + dz * g_Rmat[6] + g_tb[0] + c0;
    float p1y = dx * g_Rmat[1] + dy * g_Rmat[4] + dz * g_Rmat[7] + g_tb[1] + c1;
    float p1z = dx * g_Rmat[2] + dy * g_Rmat[5] + dz * g_Rmat[8] + g_tb[2] + c2;
    out[i * 3] = (p1x - p0x) * DT_INV;
    out[i * 3 + 1] = (p1y - p0y) * DT_INV;
    out[i * 3 + 2] = (p1z - p0z) * DT_INV;
}

// ---------------- fluid predictor: 128 -> 128 -> 128 -> 3 ----------------
__global__ void __launch_bounds__(NT) k_fluid(const float* __restrict__ eff,
                                              const float* __restrict__ fb0,
                                              const float* __restrict__ fb1,
                                              const float* __restrict__ fw2,
                                              const float* __restrict__ fb2,
                                              float* __restrict__ out) {
    extern __shared__ float sm[];
    float* bufA = sm;
    float* bufB = sm + 128 * PITCH;
    float* sW = sm + 2 * 128 * PITCH;
    int t = threadIdx.x;
    int p0 = RIGN + blockIdx.x * 128;
    int fg = t & 31, rbase = (t >> 5) * 8;
    ull acc[4][4];
    stage_rows(bufA, eff + (size_t)p0 * 128);
    stage_w(sW, g_flT0, 128 * 128);
    __syncthreads();
    init_bias2(acc, fb0, fg);
    mlp_acc2(bufA, sW, 128, fg, rbase, acc);
    store_hT2(bufB, acc, fg, rbase);
    __syncthreads();
    stage_w(sW, g_flT1, 128 * 128);
    __syncthreads();
    init_bias2(acc, fb1, fg);
    mlp_acc2(bufB, sW, 128, fg, rbase, acc);
    store_hT2(bufA, acc, fg, rbase);
    __syncthreads();
    // final 128 -> 3 layer: groups 0..2 each compute one output channel
    {
        int row = t & 127, grp = t >> 7;
        if (grp < 3) {
            float o = fb2[grp];
            const float* wr = fw2 + grp * 128;
            for (int k = 0; k < 128; ++k) o = fmaf(wr[k], bufA[k * PITCH + row], o);
            out[(size_t)(p0 + row) * 3 + grp] = o;
        }
    }
}

// ---------------- launch ----------------
extern "C" void kernel_launch(void* const* d_in, const int* in_sizes, int n_in,
                              void* d_out, int out_size) {
    const float* state = (const float*)d_in[0];
    const float* attr = (const float*)d_in[1];
    const float* Ra = (const float*)d_in[2];
    const int* recv = (const int*)d_in[3];
    const int* send = (const int*)d_in[4];
    const float* pe_w0 = (const float*)d_in[5];
    const float* pe_b0 = (const float*)d_in[6];
    const float* pe_w1 = (const float*)d_in[7];
    const float* pe_b1 = (const float*)d_in[8];
    const float* re_w0 = (const float*)d_in[9];
    const float* re_b0 = (const float*)d_in[10];
    const float* re_w1 = (const float*)d_in[11];
    const float* re_b1 = (const float*)d_in[12];
    const float* re_w2 = (const float*)d_in[13];
    const float* re_b2 = (const float*)d_in[14];
    const float* rp_w = (const float*)d_in[15];
    const float* rp_b = (const float*)d_in[16];
    const float* pp_w = (const float*)d_in[17];
    const float* pp_b = (const float*)d_in[18];
    const float* rg_w0 = (const float*)d_in[19];
    const float* rg_b0 = (const float*)d_in[20];
    const float* rg_w1 = (const float*)d_in[21];
    const float* rg_b1 = (const float*)d_in[22];
    const float* rg_w2 = (const float*)d_in[23];
    const float* rg_b2 = (const float*)d_in[24];
    const float* fl_w0 = (const float*)d_in[25];
    const float* fl_b0 = (const float*)d_in[26];
    const float* fl_w1 = (const float*)d_in[27];
    const float* fl_b1 = (const float*)d_in[28];
    const float* fl_w2 = (const float*)d_in[29];
    const float* fl_b2 = (const float*)d_in[30];
    float* out = (float*)d_out;

    cudaFuncSetAttribute(k_pe, cudaFuncAttributeMaxDynamicSharedMemorySize, SMEM_BYTES);
    cudaFuncSetAttribute(k_rel, cudaFuncAttributeMaxDynamicSharedMemorySize, SMEM_BYTES);
    cudaFuncSetAttribute(k_prop, cudaFuncAttributeMaxDynamicSharedMemorySize, SMEM_BYTES);
    cudaFuncSetAttribute(k_pupdate, cudaFuncAttributeMaxDynamicSharedMemorySize, SMEM_BYTES);
    cudaFuncSetAttribute(k_fluid, cudaFuncAttributeMaxDynamicSharedMemorySize, SMEM_BYTES);

    float *aggp, *pooledp, *effAp, *effBp;
    cudaGetSymbolAddress((void**)&aggp, g_agg);
    cudaGetSymbolAddress((void**)&pooledp, g_pooled);
    cudaGetSymbolAddress((void**)&effAp, g_effA);
    cudaGetSymbolAddress((void**)&effBp, g_effB);

    // setup: transpose all weights to [K][128] in one launch
    k_transpose_all<<<664, 256>>>(pe_w0, pe_w1, re_w0, re_w1, re_w2, rp_w, pp_w, fl_w0, fl_w1);

    k_centroid<<<1, 256>>>(state);
    k_pe<<<NP / 128, NT, SMEM_BYTES>>>(state, attr, pe_b0, pe_b1);
    k_rel<<<NE / 128, NT, SMEM_BYTES>>>(state, attr, Ra, recv, send, re_b0, re_b1, re_b2);

    // propagation step 1 (effect == 0 -> skip eff chunks)
    cudaMemsetAsync(aggp, 0, (size_t)NP * NF * sizeof(float));
    k_prop<<<NE / 128, NT, SMEM_BYTES>>>(recv, send, effAp, rp_b, 0);
    k_pupdate<<<NP / 128, NT, SMEM_BYTES>>>(pp_b, effAp);

    // propagation step 2
    cudaMemsetAsync(aggp, 0, (size_t)NP * NF * sizeof(float));
    k_prop<<<NE / 128, NT, SMEM_BYTES>>>(recv, send, effAp, rp_b, 1);
    k_pupdate<<<NP / 128, NT, SMEM_BYTES>>>(pp_b, effBp);

    // rigid branch
    cudaMemsetAsync(pooledp, 0, NF * sizeof(float));
    k_pool<<<RIGN / 128, 128>>>(effBp);
    k_rigid_mlp<<<1, 128>>>(rg_w0, rg_b0, rg_w1, rg_b1, rg_w2, rg_b2);
    k_rigid_out<<<RIGN / 256, 256>>>(state, out);

    // fluid branch
    k_fluid<<<(NP - RIGN) / 128, NT, SMEM_BYTES>>>(effBp, fl_b0, fl_b1, fl_w2, fl_b2, out);
}

// round 7
// speedup vs baseline: 1.4642x; 1.0015x over previous
#include <cuda_runtime.h>
#include <cstddef>

#define NP 65536
#define NE 524288
#define RIGN 4096
#define NF 128
#define PITCH 130
#define NT 512
#define DT_INV 60.0f

typedef unsigned long long ull;

// ---------------- scratch (device globals; no allocation allowed) ----------------
__device__ float g_cent[6];
__device__ float g_pooled[NF];
__device__ float g_Rmat[9];
__device__ float g_tb[3];
__device__ float g_pe[(size_t)NP * NF];
__device__ float g_rel[(size_t)NE * NF];
__device__ float g_effA[(size_t)NP * NF];
__device__ float g_effB[(size_t)NP * NF];
__device__ float g_agg[(size_t)NP * NF];
// transposed weights, layout [K][128]
__device__ float g_peT0[15 * 128];
__device__ float g_peT1[128 * 128];
__device__ float g_reT0[31 * 128];
__device__ float g_reT1[128 * 128];
__device__ float g_reT2[128 * 128];
__device__ float g_rpT[384 * 128];
__device__ float g_ppT[256 * 128];
__device__ float g_flT0[128 * 128];
__device__ float g_flT1[128 * 128];

#define SMEM_BYTES ((2 * 128 * PITCH + 128 * 128) * 4)

// ---------------- f32x2 helpers ----------------
__device__ __forceinline__ ull ffma2(ull a, ull b, ull c) {
    ull d;
    asm("fma.rn.f32x2 %0, %1, %2, %3;" : "=l"(d) : "l"(a), "l"(b), "l"(c));
    return d;
}
__device__ __forceinline__ ull pack2(float lo, float hi) {
    ull r;
    asm("mov.b64 %0, {%1, %2};" : "=l"(r) : "f"(lo), "f"(hi));
    return r;
}
__device__ __forceinline__ float2 unpack2(ull v) {
    float2 f;
    asm("mov.b64 {%0, %1}, %2;" : "=f"(f.x), "=f"(f.y) : "l"(v));
    return f;
}

// ---------------- setup kernels ----------------
__global__ void k_transpose_all(const float* __restrict__ pe_w0, const float* __restrict__ pe_w1,
                                const float* __restrict__ re_w0, const float* __restrict__ re_w1,
                                const float* __restrict__ re_w2, const float* __restrict__ rp_w,
                                const float* __restrict__ pp_w, const float* __restrict__ fl_w0,
                                const float* __restrict__ fl_w1) {
    int b = blockIdx.x;
    const float* src;
    float* dst;
    int K, base;
    if (b < 8)        { src = pe_w0; dst = g_peT0; K = 15;  base = 0; }
    else if (b < 72)  { src = pe_w1; dst = g_peT1; K = 128; base = 8; }
    else if (b < 88)  { src = re_w0; dst = g_reT0; K = 31;  base = 72; }
    else if (b < 152) { src = re_w1; dst = g_reT1; K = 128; base = 88; }
    else if (b < 216) { src = re_w2; dst = g_reT2; K = 128; base = 152; }
    else if (b < 408) { src = rp_w;  dst = g_rpT;  K = 384; base = 216; }
    else if (b < 536) { src = pp_w;  dst = g_ppT;  K = 256; base = 408; }
    else if (b < 600) { src = fl_w0; dst = g_flT0; K = 128; base = 536; }
    else              { src = fl_w1; dst = g_flT1; K = 128; base = 600; }
    int idx = (b - base) * 256 + threadIdx.x;
    if (idx < K * 128) {
        int k = idx >> 7, f = idx & 127;
        dst[idx] = src[f * K + k];
    }
}

__global__ void k_centroid(const float* __restrict__ state) {
    __shared__ float red[256];
    float s[6] = {0, 0, 0, 0, 0, 0};
    for (int r = threadIdx.x; r < RIGN; r += 256) {
#pragma unroll
        for (int c = 0; c < 6; ++c) s[c] += state[r * 6 + c];
    }
#pragma unroll
    for (int c = 0; c < 6; ++c) {
        red[threadIdx.x] = s[c];
        __syncthreads();
        for (int off = 128; off > 0; off >>= 1) {
            if (threadIdx.x < off) red[threadIdx.x] += red[threadIdx.x + off];
            __syncthreads();
        }
        if (threadIdx.x == 0) g_cent[c] = red[0] * (1.0f / RIGN);
        __syncthreads();
    }
}

// ---------------- shared helpers ----------------
__device__ __forceinline__ void stage_w(float* sW, const float* __restrict__ g, int nelem) {
    int n4 = nelem >> 2;
    const float4* g4 = (const float4*)g;
    float4* s4 = (float4*)sW;
    for (int i = threadIdx.x; i < n4; i += NT) s4[i] = g4[i];
}

// load 128 contiguous rows of 128 floats (row-major) -> smem transposed pitch-130
__device__ __forceinline__ void stage_rows(float* sX, const float* __restrict__ g) {
    for (int i = threadIdx.x; i < 128 * 128; i += NT) {
        int r = i >> 7, k = i & 127;
        sX[k * PITCH + r] = g[i];
    }
}

__device__ __forceinline__ void init_bias2(ull acc[4][4], const float* __restrict__ b, int fg) {
#pragma unroll
    for (int j = 0; j < 4; ++j) {
        float bj = b[fg + 32 * j];
        ull bp = pack2(bj, bj);
#pragma unroll
        for (int p = 0; p < 4; ++p) acc[p][j] = bp;
    }
}

// core GEMM tile: 128 rows x 128 feats, each thread 8 rows (as 4 pairs) x 4 feats
__device__ __forceinline__ void mlp_acc2(const float* sX, const float* sW, int K,
                                         int fg, int rbase, ull acc[4][4]) {
    for (int k = 0; k < K; ++k) {
        const float* wr = sW + k * 128 + fg;
        ull w0 = pack2(wr[0], wr[0]);
        ull w1 = pack2(wr[32], wr[32]);
        ull w2 = pack2(wr[64], wr[64]);
        ull w3 = pack2(wr[96], wr[96]);
        const ull* xr = (const ull*)(sX + k * PITCH + rbase);
#pragma unroll
        for (int p = 0; p < 4; ++p) {
            ull x = xr[p];
            acc[p][0] = ffma2(x, w0, acc[p][0]);
            acc[p][1] = ffma2(x, w1, acc[p][1]);
            acc[p][2] = ffma2(x, w2, acc[p][2]);
            acc[p][3] = ffma2(x, w3, acc[p][3]);
        }
    }
}

// relu + store hidden activations back to smem (transposed), 64-bit stores
__device__ __forceinline__ void store_hT2(float* sH, const ull acc[4][4], int fg, int rbase) {
#pragma unroll
    for (int j = 0; j < 4; ++j) {
        ull* d = (ull*)(sH + (fg + 32 * j) * PITCH + rbase);
#pragma unroll
        for (int p = 0; p < 4; ++p) {
            float2 v = unpack2(acc[p][j]);
            d[p] = pack2(fmaxf(v.x, 0.0f), fmaxf(v.y, 0.0f));
        }
    }
}

// relu + store to global row-major [row][128]
__device__ __forceinline__ void store_gout(float* __restrict__ g, const ull acc[4][4],
                                           int fg, int rbase, int p0) {
#pragma unroll
    for (int p = 0; p < 4; ++p) {
#pragma unroll
        for (int j = 0; j < 4; ++j) {
            float2 v = unpack2(acc[p][j]);
            g[(size_t)(p0 + rbase + 2 * p) * 128 + fg + 32 * j] = fmaxf(v.x, 0.0f);
            g[(size_t)(p0 + rbase + 2 * p + 1) * 128 + fg + 32 * j] = fmaxf(v.y, 0.0f);
        }
    }
}

// ---------------- particle encoder: [attr2, state](15) -> 128 -> 128 ----------------
__global__ void __launch_bounds__(NT) k_pe(const float* __restrict__ state,
                                           const float* __restrict__ attr,
                                           const float* __restrict__ b0,
                                           const float* __restrict__ b1) {
    extern __shared__ float sm[];
    float* bufA = sm;
    float* bufB = sm + 128 * PITCH;
    float* sW = sm + 2 * 128 * PITCH;
    int t = threadIdx.x;
    int p0 = blockIdx.x * 128;
    int row = t & 127, grp = t >> 7;
    {
        int p = p0 + row;
        if (grp == 0) {
            bufA[0 * PITCH + row] = attr[p * 3];
            bufA[1 * PITCH + row] = attr[p * 3 + 1];
            bufA[2 * PITCH + row] = attr[p * 3 + 2];
        } else if (grp == 1) {
#pragma unroll
            for (int c = 0; c < 6; ++c) {
                float s = state[p * 6 + c];
                bufA[(3 + c) * PITCH + row] = (p < RIGN) ? (s - g_cent[c]) : 0.0f;
            }
        } else if (grp == 2) {
#pragma unroll
            for (int c = 0; c < 6; ++c) bufA[(9 + c) * PITCH + row] = state[p * 6 + c];
        }
    }
    stage_w(sW, g_peT0, 15 * 128);
    __syncthreads();
    int fg = t & 31, rbase = (t >> 5) * 8;
    ull acc[4][4];
    init_bias2(acc, b0, fg);
    mlp_acc2(bufA, sW, 15, fg, rbase, acc);
    store_hT2(bufB, acc, fg, rbase);
    __syncthreads();
    stage_w(sW, g_peT1, 128 * 128);
    __syncthreads();
    init_bias2(acc, b1, fg);
    mlp_acc2(bufB, sW, 128, fg, rbase, acc);
    store_gout(g_pe, acc, fg, rbase, p0);
}

// ---------------- relation encoder: 31 -> 128 -> 128 -> 128 ----------------
__global__ void __launch_bounds__(NT) k_rel(const float* __restrict__ state,
                                            const float* __restrict__ attr,
                                            const float* __restrict__ Ra,
                                            const int* __restrict__ recv,
                                            const int* __restrict__ send,
                                            const float* __restrict__ b0,
                                            const float* __restrict__ b1,
                                            const float* __restrict__ b2) {
    extern __shared__ float sm[];
    float* bufA = sm;
    float* bufB = sm + 128 * PITCH;
    float* sW = sm + 2 * 128 * PITCH;
    int t = threadIdx.x;
    int e0 = blockIdx.x * 128;
    int row = t & 127, grp = t >> 7;
    {
        int e = e0 + row;
        if (grp == 0) {           // recv attr + recv offset
            int rv = recv[e];
#pragma unroll
            for (int c = 0; c < 3; ++c) bufA[c * PITCH + row] = attr[rv * 3 + c];
#pragma unroll
            for (int c = 0; c < 6; ++c) {
                float s = state[rv * 6 + c];
                bufA[(3 + c) * PITCH + row] = (rv < RIGN) ? (s - g_cent[c]) : 0.0f;
            }
        } else if (grp == 1) {    // send attr + send offset
            int sd = send[e];
#pragma unroll
            for (int c = 0; c < 3; ++c) bufA[(9 + c) * PITCH + row] = attr[sd * 3 + c];
#pragma unroll
            for (int c = 0; c < 6; ++c) {
                float s = state[sd * 6 + c];
                bufA[(12 + c) * PITCH + row] = (sd < RIGN) ? (s - g_cent[c]) : 0.0f;
            }
        } else if (grp == 2) {    // recv state
            int rv = recv[e];
#pragma unroll
            for (int c = 0; c < 6; ++c) bufA[(18 + c) * PITCH + row] = state[rv * 6 + c];
        } else {                  // send state + Ra
            int sd = send[e];
#pragma unroll
            for (int c = 0; c < 6; ++c) bufA[(24 + c) * PITCH + row] = state[sd * 6 + c];
            bufA[30 * PITCH + row] = Ra[e];
        }
    }
    stage_w(sW, g_reT0, 31 * 128);
    __syncthreads();
    int fg = t & 31, rbase = (t >> 5) * 8;
    ull acc[4][4];
    init_bias2(acc, b0, fg);
    mlp_acc2(bufA, sW, 31, fg, rbase, acc);
    store_hT2(bufB, acc, fg, rbase);
    __syncthreads();
    stage_w(sW, g_reT1, 128 * 128);
    __syncthreads();
    init_bias2(acc, b1, fg);
    mlp_acc2(bufB, sW, 128, fg, rbase, acc);
    store_hT2(bufA, acc, fg, rbase);
    __syncthreads();
    stage_w(sW, g_reT2, 128 * 128);
    __syncthreads();
    init_bias2(acc, b2, fg);
    mlp_acc2(bufA, sW, 128, fg, rbase, acc);
    store_gout(g_rel, acc, fg, rbase, e0);
}

// gather 128 rows of effect[idx[e]] -> smem transposed; all NT threads participate
__device__ __forceinline__ void stage_gather(float* sX, const float* __restrict__ eff,
                                             const int* __restrict__ idx, int e0) {
    int t = threadIdx.x;
    int row = t & 127, kq = t >> 7;  // kq in 0..3, each covers 32 k
    int v = idx[e0 + row];
    const float4* s4 = (const float4*)(eff + (size_t)v * 128 + kq * 32);
#pragma unroll
    for (int k4 = 0; k4 < 8; ++k4) {
        float4 w = s4[k4];
        int k = kq * 32 + 4 * k4;
        sX[k * PITCH + row] = w.x;
        sX[(k + 1) * PITCH + row] = w.y;
        sX[(k + 2) * PITCH + row] = w.z;
        sX[(k + 3) * PITCH + row] = w.w;
    }
}

// ---------------- propagation edge pass ----------------
__global__ void __launch_bounds__(NT) k_prop(const int* __restrict__ recv,
                                             const int* __restrict__ send,
                                             const float* __restrict__ eff,
                                             const float* __restrict__ rp_b, int use_eff) {
    extern __shared__ float sm[];
    float* bufA = sm;
    float* sW = sm + 2 * 128 * PITCH;
    int t = threadIdx.x;
    int e0 = blockIdx.x * 128;
    int fg = t & 31, rbase = (t >> 5) * 8;
    ull acc[4][4];
    init_bias2(acc, rp_b, fg);
    // chunk 0: relation_encode rows
    stage_rows(bufA, g_rel + (size_t)e0 * 128);
    stage_w(sW, g_rpT, 128 * 128);
    __syncthreads();
    mlp_acc2(bufA, sW, 128, fg, rbase, acc);
    if (use_eff) {
        // chunk 1: eff[recv]
        __syncthreads();
        stage_gather(bufA, eff, recv, e0);
        stage_w(sW, g_rpT + 128 * 128, 128 * 128);
        __syncthreads();
        mlp_acc2(bufA, sW, 128, fg, rbase, acc);
        // chunk 2: eff[send]
        __syncthreads();
        stage_gather(bufA, eff, send, e0);
        stage_w(sW, g_rpT + 2 * 128 * 128, 128 * 128);
        __syncthreads();
        mlp_acc2(bufA, sW, 128, fg, rbase, acc);
    }
    // scatter-add relu(rel_eff) into agg[recv]
#pragma unroll
    for (int p = 0; p < 4; ++p) {
        int e = e0 + rbase + 2 * p;
        int rv0 = recv[e], rv1 = recv[e + 1];
        float* d0 = g_agg + (size_t)rv0 * 128 + fg;
        float* d1 = g_agg + (size_t)rv1 * 128 + fg;
#pragma unroll
        for (int j = 0; j < 4; ++j) {
            float2 v = unpack2(acc[p][j]);
            atomicAdd(d0 + 32 * j, fmaxf(v.x, 0.0f));
            atomicAdd(d1 + 32 * j, fmaxf(v.y, 0.0f));
        }
    }
}

// ---------------- particle update: relu(pp_w @ [pe, agg]) ----------------
__global__ void __launch_bounds__(NT) k_pupdate(const float* __restrict__ pp_b,
                                                float* __restrict__ eff_out) {
    extern __shared__ float sm[];
    float* bufA = sm;
    float* sW = sm + 2 * 128 * PITCH;
    int t = threadIdx.x;
    int p0 = blockIdx.x * 128;
    int fg = t & 31, rbase = (t >> 5) * 8;
    ull acc[4][4];
    init_bias2(acc, pp_b, fg);
    stage_rows(bufA, g_pe + (size_t)p0 * 128);
    stage_w(sW, g_ppT, 128 * 128);
    __syncthreads();
    mlp_acc2(bufA, sW, 128, fg, rbase, acc);
    __syncthreads();
    stage_rows(bufA, g_agg + (size_t)p0 * 128);
    stage_w(sW, g_ppT + 128 * 128, 128 * 128);
    __syncthreads();
    mlp_acc2(bufA, sW, 128, fg, rbase, acc);
    store_gout(eff_out, acc, fg, rbase, p0);
}

// ---------------- rigid pooling + small MLP + rigid output ----------------
__global__ void k_pool(const float* __restrict__ eff) {
    int f = threadIdx.x;  // 128
    int r0 = blockIdx.x * 128;
    float s = 0.0f;
    for (int r = 0; r < 128; ++r) s += eff[(size_t)(r0 + r) * 128 + f];
    atomicAdd(&g_pooled[f], s);
}

__global__ void k_rigid_mlp(const float* __restrict__ w0, const float* __restrict__ b0,
                            const float* __restrict__ w1, const float* __restrict__ b1,
                            const float* __restrict__ w2, const float* __restrict__ b2) {
    __shared__ float pin[128], h0[128], h1[128], tt[7];
    int t = threadIdx.x;  // 128
    pin[t] = g_pooled[t] * (1.0f / RIGN);
    __syncthreads();
    float s = b0[t];
    for (int k = 0; k < 128; ++k) s = fmaf(w0[t * 128 + k], pin[k], s);
    h0[t] = fmaxf(s, 0.0f);
    __syncthreads();
    s = b1[t];
    for (int k = 0; k < 128; ++k) s = fmaf(w1[t * 128 + k], h0[k], s);
    h1[t] = fmaxf(s, 0.0f);
    __syncthreads();
    if (t < 7) {
        s = b2[t];
        for (int k = 0; k < 128; ++k) s = fmaf(w2[t * 128 + k], h1[k], s);
        tt[t] = s;
    }
    __syncthreads();
    if (t == 0) {
        float qw = tt[0], qx = tt[1], qy = tt[2], qz = tt[3];
        float inv = rsqrtf(qw * qw + qx * qx + qy * qy + qz * qz);
        qw *= inv; qx *= inv; qy *= inv; qz *= inv;
        g_Rmat[0] = 1.0f - 2.0f * (qy * qy + qz * qz);
        g_Rmat[1] = 2.0f * (qx * qy + qz * qw);
        g_Rmat[2] = 2.0f * (qx * qz - qy * qw);
        g_Rmat[3] = 2.0f * (qx * qy - qz * qw);
        g_Rmat[4] = 1.0f - 2.0f * (qx * qx + qz * qz);
        g_Rmat[5] = 2.0f * (qy * qz + qx * qw);
        g_Rmat[6] = 2.0f * (qx * qz + qy * qw);
        g_Rmat[7] = 2.0f * (qy * qz - qx * qw);
        g_Rmat[8] = 1.0f - 2.0f * (qx * qx + qy * qy);
        g_tb[0] = tt[4]; g_tb[1] = tt[5]; g_tb[2] = tt[6];
    }
}

__global__ void k_rigid_out(const float* __restrict__ state, float* __restrict__ out) {
    int i = blockIdx.x * 256 + threadIdx.x;
    if (i >= RIGN) return;
    float c0 = g_cent[0], c1 = g_cent[1], c2 = g_cent[2];
    float p0x = state[i * 6], p0y = state[i * 6 + 1], p0z = state[i * 6 + 2];
    float dx = p0x - c0, dy = p0y - c1, dz = p0z - c2;
    float p1x = dx * g_Rmat[0] + dy * g_Rmat[3] + dz * g_Rmat[6] + g_tb[0] + c0;
    float p1y = dx * g_Rmat[1] + dy * g_Rmat[4] + dz * g_Rmat[7] + g_tb[1] + c1;
    float p1z = dx * g_Rmat[2] + dy * g_Rmat[5] + dz * g_Rmat[8] + g_tb[2] + c2;
    out[i * 3] = (p1x - p0x) * DT_INV;
    out[i * 3 + 1] = (p1y - p0y) * DT_INV;
    out[i * 3 + 2] = (p1z - p0z) * DT_INV;
}

// ---------------- fluid predictor: 128 -> 128 -> 128 -> 3 ----------------
__global__ void __launch_bounds__(NT) k_fluid(const float* __restrict__ eff,
                                              const float* __restrict__ fb0,
                                              const float* __restrict__ fb1,
                                              const float* __restrict__ fw2,
                                              const float* __restrict__ fb2,
                                              float* __restrict__ out) {
    extern __shared__ float sm[];
    float* bufA = sm;
    float* bufB = sm + 128 * PITCH;
    float* sW = sm + 2 * 128 * PITCH;
    int t = threadIdx.x;
    int p0 = RIGN + blockIdx.x * 128;
    int fg = t & 31, rbase = (t >> 5) * 8;
    ull acc[4][4];
    stage_rows(bufA, eff + (size_t)p0 * 128);
    stage_w(sW, g_flT0, 128 * 128);
    __syncthreads();
    init_bias2(acc, fb0, fg);
    mlp_acc2(bufA, sW, 128, fg, rbase, acc);
    store_hT2(bufB, acc, fg, rbase);
    __syncthreads();
    stage_w(sW, g_flT1, 128 * 128);
    __syncthreads();
    init_bias2(acc, fb1, fg);
    mlp_acc2(bufB, sW, 128, fg, rbase, acc);
    store_hT2(bufA, acc, fg, rbase);
    __syncthreads();
    // final 128 -> 3 layer: groups 0..2 each compute one output channel
    {
        int row = t & 127, grp = t >> 7;
        if (grp < 3) {
            float o = fb2[grp];
            const float* wr = fw2 + grp * 128;
            for (int k = 0; k < 128; ++k) o = fmaf(wr[k], bufA[k * PITCH + row], o);
            out[(size_t)(p0 + row) * 3 + grp] = o;
        }
    }
}

// ---------------- launch ----------------
extern "C" void kernel_launch(void* const* d_in, const int* in_sizes, int n_in,
                              void* d_out, int out_size) {
    const float* state = (const float*)d_in[0];
    const float* attr = (const float*)d_in[1];
    const float* Ra = (const float*)d_in[2];
    const int* recv = (const int*)d_in[3];
    const int* send = (const int*)d_in[4];
    const float* pe_w0 = (const float*)d_in[5];
    const float* pe_b0 = (const float*)d_in[6];
    const float* pe_w1 = (const float*)d_in[7];
    const float* pe_b1 = (const float*)d_in[8];
    const float* re_w0 = (const float*)d_in[9];
    const float* re_b0 = (const float*)d_in[10];
    const float* re_w1 = (const float*)d_in[11];
    const float* re_b1 = (const float*)d_in[12];
    const float* re_w2 = (const float*)d_in[13];
    const float* re_b2 = (const float*)d_in[14];
    const float* rp_w = (const float*)d_in[15];
    const float* rp_b = (const float*)d_in[16];
    const float* pp_w = (const float*)d_in[17];
    const float* pp_b = (const float*)d_in[18];
    const float* rg_w0 = (const float*)d_in[19];
    const float* rg_b0 = (const float*)d_in[20];
    const float* rg_w1 = (const float*)d_in[21];
    const float* rg_b1 = (const float*)d_in[22];
    const float* rg_w2 = (const float*)d_in[23];
    const float* rg_b2 = (const float*)d_in[24];
    const float* fl_w0 = (const float*)d_in[25];
    const float* fl_b0 = (const float*)d_in[26];
    const float* fl_w1 = (const float*)d_in[27];
    const float* fl_b1 = (const float*)d_in[28];
    const float* fl_w2 = (const float*)d_in[29];
    const float* fl_b2 = (const float*)d_in[30];
    float* out = (float*)d_out;

    cudaFuncSetAttribute(k_pe, cudaFuncAttributeMaxDynamicSharedMemorySize, SMEM_BYTES);
    cudaFuncSetAttribute(k_rel, cudaFuncAttributeMaxDynamicSharedMemorySize, SMEM_BYTES);
    cudaFuncSetAttribute(k_prop, cudaFuncAttributeMaxDynamicSharedMemorySize, SMEM_BYTES);
    cudaFuncSetAttribute(k_pupdate, cudaFuncAttributeMaxDynamicSharedMemorySize, SMEM_BYTES);
    cudaFuncSetAttribute(k_fluid, cudaFuncAttributeMaxDynamicSharedMemorySize, SMEM_BYTES);

    float *aggp, *pooledp, *effAp, *effBp;
    cudaGetSymbolAddress((void**)&aggp, g_agg);
    cudaGetSymbolAddress((void**)&pooledp, g_pooled);
    cudaGetSymbolAddress((void**)&effAp, g_effA);
    cudaGetSymbolAddress((void**)&effBp, g_effB);

    // setup: transpose all weights to [K][128] in one launch
    k_transpose_all<<<664, 256>>>(pe_w0, pe_w1, re_w0, re_w1, re_w2, rp_w, pp_w, fl_w0, fl_w1);

    k_centroid<<<1, 256>>>(state);
    k_pe<<<NP / 128, NT, SMEM_BYTES>>>(state, attr, pe_b0, pe_b1);
    k_rel<<<NE / 128, NT, SMEM_BYTES>>>(state, attr, Ra, recv, send, re_b0, re_b1, re_b2);

    // propagation step 1 (effect == 0 -> skip eff chunks)
    cudaMemsetAsync(aggp, 0, (size_t)NP * NF * sizeof(float));
    k_prop<<<NE / 128, NT, SMEM_BYTES>>>(recv, send, effAp, rp_b, 0);
    k_pupdate<<<NP / 128, NT, SMEM_BYTES>>>(pp_b, effAp);

    // propagation step 2
    cudaMemsetAsync(aggp, 0, (size_t)NP * NF * sizeof(float));
    k_prop<<<NE / 128, NT, SMEM_BYTES>>>(recv, send, effAp, rp_b, 1);
    k_pupdate<<<NP / 128, NT, SMEM_BYTES>>>(pp_b, effBp);

    // rigid branch
    cudaMemsetAsync(pooledp, 0, NF * sizeof(float));
    k_pool<<<RIGN / 128, 128>>>(effBp);
    k_rigid_mlp<<<1, 128>>>(rg_w0, rg_b0, rg_w1, rg_b1, rg_w2, rg_b2);
    k_rigid_out<<<RIGN / 256, 256>>>(state, out);

    // fluid branch
    k_fluid<<<(NP - RIGN) / 128, NT, SMEM_BYTES>>>(effBp, fl_b0, fl_b1, fl_w2, fl_b2, out);
}

// round 10
// speedup vs baseline: 2.0203x; 1.3798x over previous
#include <cuda_runtime.h>
#include <cstddef>
#include <cstdint>

#define NP 65536
#define NE 524288
#define RIGN 4096
#define DT_INV 60.0f
#define PX 132                       // X pitch in floats
#define XFLOATS (128 * PX)           // 16896 floats
#define CHUNKF 1280                  // floats per k-chunk in a weight blob
#define SMEMSZ ((XFLOATS + 16 * CHUNKF) * 4)  // 67584 + 81920 bytes

// ---------------- device globals (no allocation allowed) ----------------
__device__ float g_cent[6];
__device__ float g_pooled[128];
__device__ float g_Rmat[9];
__device__ float g_tb[3];
// row-major activation buffers
__device__ __align__(16) float g_pe[(size_t)NP * 128];
__device__ __align__(16) float g_rel[(size_t)NE * 128];
__device__ __align__(16) float g_agg[(size_t)NP * 128];
__device__ __align__(16) float g_eff1[(size_t)NP * 128];
__device__ __align__(16) float g_eff2[(size_t)NP * 128];
// pre-permuted per-thread weight blobs: [kc][h][lane][20] (16 used + 4 pad)
__device__ __align__(16) float g_bPe0[4 * CHUNKF];
__device__ __align__(16) float g_bPe1[16 * CHUNKF];
__device__ __align__(16) float g_bRe0[4 * CHUNKF];
__device__ __align__(16) float g_bRe1[16 * CHUNKF];
__device__ __align__(16) float g_bRe2[16 * CHUNKF];
__device__ __align__(16) float g_bRp[48 * CHUNKF];
__device__ __align__(16) float g_bPp[32 * CHUNKF];
__device__ __align__(16) float g_bFl0[16 * CHUNKF];
__device__ __align__(16) float g_bFl1[16 * CHUNKF];

// ---------------- helpers ----------------
__device__ __forceinline__ float totf32(float x) {
    uint32_t u;
    asm("cvt.rna.tf32.f32 %0, %1;" : "=r"(u) : "f"(x));
    return __uint_as_float(u);
}
__device__ __forceinline__ void mma_tf32(float* d, uint32_t a0, uint32_t a1, uint32_t a2,
                                         uint32_t a3, uint32_t b0, uint32_t b1) {
    asm volatile(
        "mma.sync.aligned.m16n8k8.row.col.f32.tf32.tf32.f32 "
        "{%0,%1,%2,%3}, {%4,%5,%6,%7}, {%8,%9}, {%0,%1,%2,%3};"
        : "+f"(d[0]), "+f"(d[1]), "+f"(d[2]), "+f"(d[3])
        : "r"(a0), "r"(a1), "r"(a2), "r"(a3), "r"(b0), "r"(b1));
}
__device__ __forceinline__ void red2(float* p, float v0, float v1) {
    asm volatile("red.global.add.v2.f32 [%0], {%1, %2};" :: "l"(p), "f"(v0), "f"(v1) : "memory");
}

// core: D[128,128] += X[128,K] * W^T[K,128]; 8 warps, warp tile 32 rows x 64 feats
__device__ __forceinline__ void mma_layer(const float* sX, const float* sW, int nchunks,
                                          float acc[2][8][4]) {
    int lane = threadIdx.x & 31, warp = threadIdx.x >> 5;
    int rb = (warp & 3) * 32, h = warp >> 2;
    int g = lane >> 2, tig = lane & 3;
    const float* x0 = sX + (rb + g) * PX + tig;
    const float* w0 = sW + (h * 32 + lane) * 20;
    for (int kc = 0; kc < nchunks; ++kc) {
        const float4* wb = (const float4*)(w0 + kc * CHUNKF);
        float4 bv[4];
#pragma unroll
        for (int q = 0; q < 4; ++q) bv[q] = wb[q];
        uint32_t A[2][4];
#pragma unroll
        for (int mt = 0; mt < 2; ++mt) {
            const float* xp = x0 + mt * 16 * PX + kc * 8;
            A[mt][0] = __float_as_uint(xp[0]);
            A[mt][1] = __float_as_uint(xp[8 * PX]);
            A[mt][2] = __float_as_uint(xp[4]);
            A[mt][3] = __float_as_uint(xp[8 * PX + 4]);
        }
#pragma unroll
        for (int j = 0; j < 8; ++j) {
            float4 q = bv[j >> 1];
            uint32_t b0 = __float_as_uint((j & 1) ? q.z : q.x);
            uint32_t b1 = __float_as_uint((j & 1) ? q.w : q.y);
#pragma unroll
            for (int mt = 0; mt < 2; ++mt)
                mma_tf32(acc[mt][j], A[mt][0], A[mt][1], A[mt][2], A[mt][3], b0, b1);
        }
    }
}
__device__ __forceinline__ void acc_zero(float acc[2][8][4]) {
#pragma unroll
    for (int mt = 0; mt < 2; ++mt)
#pragma unroll
        for (int j = 0; j < 8; ++j)
#pragma unroll
            for (int q = 0; q < 4; ++q) acc[mt][j][q] = 0.0f;
}
// bias + relu (+tf32 cvt) -> X in place
template <int CVT>
__device__ __forceinline__ void epi_x(float* sX, float acc[2][8][4],
                                      const float* __restrict__ bias) {
    int lane = threadIdx.x & 31, warp = threadIdx.x >> 5;
    int rb = (warp & 3) * 32, h = warp >> 2;
    int g = lane >> 2, tig = lane & 3;
#pragma unroll
    for (int j = 0; j < 8; ++j) {
        int c = h * 64 + j * 8 + tig * 2;
        float bx = __ldg(bias + c), by = __ldg(bias + c + 1);
#pragma unroll
        for (int mt = 0; mt < 2; ++mt) {
            int r = rb + mt * 16 + g;
            float v0 = fmaxf(acc[mt][j][0] + bx, 0.f);
            float v1 = fmaxf(acc[mt][j][1] + by, 0.f);
            float v2 = fmaxf(acc[mt][j][2] + bx, 0.f);
            float v3 = fmaxf(acc[mt][j][3] + by, 0.f);
            if (CVT) { v0 = totf32(v0); v1 = totf32(v1); v2 = totf32(v2); v3 = totf32(v3); }
            *(float2*)(sX + r * PX + c) = make_float2(v0, v1);
            *(float2*)(sX + (r + 8) * PX + c) = make_float2(v2, v3);
        }
    }
}
// bias + relu -> vectorized atomic scatter into g_agg[recv]
__device__ __forceinline__ void epi_scatter(const int* __restrict__ recv, int e0,
                                            float acc[2][8][4], const float* __restrict__ bias) {
    int lane = threadIdx.x & 31, warp = threadIdx.x >> 5;
    int rb = (warp & 3) * 32, h = warp >> 2;
    int g = lane >> 2, tig = lane & 3;
#pragma unroll
    for (int mt = 0; mt < 2; ++mt) {
        int ra = rb + mt * 16 + g;
        int va = __ldg(recv + e0 + ra), vb = __ldg(recv + e0 + ra + 8);
        float* pa = g_agg + (size_t)va * 128;
        float* pb = g_agg + (size_t)vb * 128;
#pragma unroll
        for (int j = 0; j < 8; ++j) {
            int c = h * 64 + j * 8 + tig * 2;
            float bx = __ldg(bias + c), by = __ldg(bias + c + 1);
            red2(pa + c, fmaxf(acc[mt][j][0] + bx, 0.f), fmaxf(acc[mt][j][1] + by, 0.f));
            red2(pb + c, fmaxf(acc[mt][j][2] + bx, 0.f), fmaxf(acc[mt][j][3] + by, 0.f));
        }
    }
}
// staging copies (256 threads)
__device__ __forceinline__ void s_copy(float* sX, const float* __restrict__ g) {
    for (int i = threadIdx.x; i < 4096; i += 256) {
        int r = i >> 5, c4 = i & 31;
        ((float4*)sX)[r * 33 + c4] = ((const float4*)g)[i];
    }
}
__device__ __forceinline__ void s_copy_cvt(float* sX, const float* __restrict__ g) {
    for (int i = threadIdx.x; i < 4096; i += 256) {
        int r = i >> 5, c4 = i & 31;
        float4 v = ((const float4*)g)[i];
        v.x = totf32(v.x); v.y = totf32(v.y); v.z = totf32(v.z); v.w = totf32(v.w);
        ((float4*)sX)[r * 33 + c4] = v;
    }
}
__device__ __forceinline__ void w_copy(float* sW, const float* __restrict__ g, int nchunks) {
    int n4 = nchunks * (CHUNKF / 4);
    for (int i = threadIdx.x; i < n4; i += 256) ((float4*)sW)[i] = ((const float4*)g)[i];
}
__device__ __forceinline__ void copy_out(float* __restrict__ g, const float* sX) {
    for (int i = threadIdx.x; i < 4096; i += 256) {
        int r = i >> 5, c4 = i & 31;
        ((float4*)g)[i] = ((const float4*)sX)[r * 33 + c4];
    }
}
// gather 128 rows src[idx[e0+r]] (row-major [p][128]) -> X
__device__ __forceinline__ void s_gather(float* sX, const float* __restrict__ src,
                                         const int* __restrict__ idx, int e0) {
    int row = threadIdx.x & 127, kq = threadIdx.x >> 7;
    int p = __ldg(idx + e0 + row);
    const float4* s4 = (const float4*)(src + (size_t)p * 128 + kq * 64);
    float4* d4 = (float4*)(sX + row * PX + kq * 64);
#pragma unroll
    for (int q = 0; q < 16; ++q) d4[q] = s4[q];
}

// ---------------- setup: weight blobs ----------------
__global__ void k_mkblob(const float* __restrict__ pe_w0, const float* __restrict__ pe_w1,
                         const float* __restrict__ re_w0, const float* __restrict__ re_w1,
                         const float* __restrict__ re_w2, const float* __restrict__ rp_w,
                         const float* __restrict__ pp_w, const float* __restrict__ fl_w0,
                         const float* __restrict__ fl_w1) {
    int b = blockIdx.x;
    const float* src; float* blob;
    int Ktot, Kval, kc, base;
    if (b < 4)         { src = pe_w0; blob = g_bPe0; Ktot = 15;  Kval = 15;  base = 0; }
    else if (b < 20)   { src = pe_w1; blob = g_bPe1; Ktot = 128; Kval = 128; base = 4; }
    else if (b < 24)   { src = re_w0; blob = g_bRe0; Ktot = 31;  Kval = 31;  base = 20; }
    else if (b < 40)   { src = re_w1; blob = g_bRe1; Ktot = 128; Kval = 128; base = 24; }
    else if (b < 56)   { src = re_w2; blob = g_bRe2; Ktot = 128; Kval = 128; base = 40; }
    else if (b < 104)  { src = rp_w;  blob = g_bRp;  Ktot = 384; Kval = 384; base = 56; }
    else if (b < 136)  { src = pp_w;  blob = g_bPp;  Ktot = 256; Kval = 256; base = 104; }
    else if (b < 152)  { src = fl_w0; blob = g_bFl0; Ktot = 128; Kval = 128; base = 136; }
    else               { src = fl_w1; blob = g_bFl1; Ktot = 128; Kval = 128; base = 152; }
    kc = b - base;
    for (int i = threadIdx.x; i < CHUNKF; i += 256) {
        int h = i / 640, rr = i % 640, lane = rr / 20, q = rr % 20;
        float v = 0.0f;
        if (q < 16) {
            int j = q >> 1, s = q & 1;
            int tig = lane & 3, g = lane >> 2;
            int k = kc * 8 + tig + 4 * s;
            int n = h * 64 + j * 8 + g;
            if (k < Kval) v = totf32(src[n * Ktot + k]);
        }
        blob[kc * CHUNKF + i] = v;
    }
}

__global__ void k_centroid(const float* __restrict__ state) {
    __shared__ float red[256];
    float s[6] = {0, 0, 0, 0, 0, 0};
    for (int r = threadIdx.x; r < RIGN; r += 256)
#pragma unroll
        for (int c = 0; c < 6; ++c) s[c] += state[r * 6 + c];
#pragma unroll
    for (int c = 0; c < 6; ++c) {
        red[threadIdx.x] = s[c];
        __syncthreads();
        for (int off = 128; off > 0; off >>= 1) {
            if (threadIdx.x < off) red[threadIdx.x] += red[threadIdx.x + off];
            __syncthreads();
        }
        if (threadIdx.x == 0) g_cent[c] = red[0] * (1.0f / RIGN);
        __syncthreads();
    }
}

// ---------------- particle encoder: 15(pad32) -> 128 -> 128 ----------------
__global__ void __launch_bounds__(256) k_pe(const float* __restrict__ state,
                                            const float* __restrict__ attr,
                                            const float* __restrict__ b0,
                                            const float* __restrict__ b1) {
    extern __shared__ float sm_[];
    float* sX = sm_;
    float* sW = sm_ + XFLOATS;
    int t = threadIdx.x;
    int p0 = blockIdx.x * 128;
    {
        int row = t & 127, grp = t >> 7;
        int p = p0 + row;
        float* xr = sX + row * PX;
        if (grp == 0) {
#pragma unroll
            for (int c = 0; c < 3; ++c) xr[c] = totf32(attr[p * 3 + c]);
#pragma unroll
            for (int c = 0; c < 6; ++c) xr[9 + c] = totf32(state[p * 6 + c]);
        } else {
#pragma unroll
            for (int c = 0; c < 6; ++c) {
                float s = state[p * 6 + c];
                xr[3 + c] = (p < RIGN) ? totf32(s - g_cent[c]) : 0.0f;
            }
            for (int c = 15; c < 32; ++c) xr[c] = 0.0f;
        }
    }
    w_copy(sW, g_bPe0, 4);
    __syncthreads();
    float acc[2][8][4];
    acc_zero(acc);
    mma_layer(sX, sW, 4, acc);
    __syncthreads();
    epi_x<1>(sX, acc, b0);
    w_copy(sW, g_bPe1, 16);
    __syncthreads();
    acc_zero(acc);
    mma_layer(sX, sW, 16, acc);
    __syncthreads();
    epi_x<1>(sX, acc, b1);
    __syncthreads();
    copy_out(g_pe + (size_t)blockIdx.x * 16384, sX);
}

// ---------------- relation encoder: 31(pad32) -> 128 -> 128 -> 128 ----------------
__global__ void __launch_bounds__(256) k_rel(const float* __restrict__ state,
                                             const float* __restrict__ attr,
                                             const float* __restrict__ Ra,
                                             const int* __restrict__ recv,
                                             const int* __restrict__ send,
                                             const float* __restrict__ b0,
                                             const float* __restrict__ b1,
                                             const float* __restrict__ b2) {
    extern __shared__ float sm_[];
    float* sX = sm_;
    float* sW = sm_ + XFLOATS;
    int t = threadIdx.x;
    int e0 = blockIdx.x * 128;
    {
        int row = t & 127, grp = t >> 7;
        int e = e0 + row;
        float* xr = sX + row * PX;
        if (grp == 0) {
            int rv = __ldg(recv + e);
#pragma unroll
            for (int c = 0; c < 3; ++c) xr[c] = totf32(attr[rv * 3 + c]);
#pragma unroll
            for (int c = 0; c < 6; ++c) {
                float s = state[rv * 6 + c];
                xr[3 + c] = (rv < RIGN) ? totf32(s - g_cent[c]) : 0.0f;
                xr[18 + c] = totf32(s);
            }
        } else {
            int sd = __ldg(send + e);
#pragma unroll
            for (int c = 0; c < 3; ++c) xr[9 + c] = totf32(attr[sd * 3 + c]);
#pragma unroll
            for (int c = 0; c < 6; ++c) {
                float s = state[sd * 6 + c];
                xr[12 + c] = (sd < RIGN) ? totf32(s - g_cent[c]) : 0.0f;
                xr[24 + c] = totf32(s);
            }
            xr[30] = totf32(Ra[e]);
            xr[31] = 0.0f;
        }
    }
    w_copy(sW, g_bRe0, 4);
    __syncthreads();
    float acc[2][8][4];
    acc_zero(acc);
    mma_layer(sX, sW, 4, acc);
    __syncthreads();
    epi_x<1>(sX, acc, b0);
    w_copy(sW, g_bRe1, 16);
    __syncthreads();
    acc_zero(acc);
    mma_layer(sX, sW, 16, acc);
    __syncthreads();
    epi_x<1>(sX, acc, b1);
    w_copy(sW, g_bRe2, 16);
    __syncthreads();
    acc_zero(acc);
    mma_layer(sX, sW, 16, acc);
    __syncthreads();
    epi_x<1>(sX, acc, b2);
    __syncthreads();
    copy_out(g_rel + (size_t)blockIdx.x * 16384, sX);
}

// ---------------- propagation edge pass ----------------
__global__ void __launch_bounds__(256) k_prop(const int* __restrict__ recv,
                                              const int* __restrict__ send,
                                              const float* __restrict__ eff,
                                              const float* __restrict__ rp_b, int use_eff) {
    extern __shared__ float sm_[];
    float* sX = sm_;
    float* sW = sm_ + XFLOATS;
    int e0 = blockIdx.x * 128;
    s_copy(sX, g_rel + (size_t)blockIdx.x * 16384);
    w_copy(sW, g_bRp, 16);
    __syncthreads();
    float acc[2][8][4];
    acc_zero(acc);
    mma_layer(sX, sW, 16, acc);
    if (use_eff) {
        __syncthreads();
        s_gather(sX, eff, recv, e0);
        w_copy(sW, g_bRp + 16 * CHUNKF, 16);
        __syncthreads();
        mma_layer(sX, sW, 16, acc);
        __syncthreads();
        s_gather(sX, eff, send, e0);
        w_copy(sW, g_bRp + 32 * CHUNKF, 16);
        __syncthreads();
        mma_layer(sX, sW, 16, acc);
    }
    epi_scatter(recv, e0, acc, rp_b);
}

// ---------------- particle update: [pe, agg] -> 128 ----------------
__global__ void __launch_bounds__(256) k_pupdate(const float* __restrict__ pp_b,
                                                 float* __restrict__ effOut) {
    extern __shared__ float sm_[];
    float* sX = sm_;
    float* sW = sm_ + XFLOATS;
    s_copy(sX, g_pe + (size_t)blockIdx.x * 16384);
    w_copy(sW, g_bPp, 16);
    __syncthreads();
    float acc[2][8][4];
    acc_zero(acc);
    mma_layer(sX, sW, 16, acc);
    __syncthreads();
    s_copy_cvt(sX, g_agg + (size_t)blockIdx.x * 16384);
    w_copy(sW, g_bPp + 16 * CHUNKF, 16);
    __syncthreads();
    mma_layer(sX, sW, 16, acc);
    __syncthreads();
    epi_x<1>(sX, acc, pp_b);
    __syncthreads();
    copy_out(effOut + (size_t)blockIdx.x * 16384, sX);
}

// ---------------- rigid pooling + small MLP + rigid output ----------------
__global__ void k_pool(const float* __restrict__ eff) {
    int f = threadIdx.x;  // 128
    int r0 = blockIdx.x * 128;
    float s = 0.0f;
    for (int r = 0; r < 128; ++r) s += eff[(size_t)(r0 + r) * 128 + f];
    atomicAdd(&g_pooled[f], s);
}

__global__ void k_rigid_mlp(const float* __restrict__ w0, const float* __restrict__ b0,
                            const float* __restrict__ w1, const float* __restrict__ b1,
                            const float* __restrict__ w2, const float* __restrict__ b2) {
    __shared__ float pin[128], h0[128], h1[128], tt[7];
    int t = threadIdx.x;  // 128
    pin[t] = g_pooled[t] * (1.0f / RIGN);
    __syncthreads();
    float s = b0[t];
    for (int k = 0; k < 128; ++k) s = fmaf(w0[t * 128 + k], pin[k], s);
    h0[t] = fmaxf(s, 0.0f);
    __syncthreads();
    s = b1[t];
    for (int k = 0; k < 128; ++k) s = fmaf(w1[t * 128 + k], h0[k], s);
    h1[t] = fmaxf(s, 0.0f);
    __syncthreads();
    if (t < 7) {
        s = b2[t];
        for (int k = 0; k < 128; ++k) s = fmaf(w2[t * 128 + k], h1[k], s);
        tt[t] = s;
    }
    __syncthreads();
    if (t == 0) {
        float qw = tt[0], qx = tt[1], qy = tt[2], qz = tt[3];
        float inv = rsqrtf(qw * qw + qx * qx + qy * qy + qz * qz);
        qw *= inv; qx *= inv; qy *= inv; qz *= inv;
        g_Rmat[0] = 1.0f - 2.0f * (qy * qy + qz * qz);
        g_Rmat[1] = 2.0f * (qx * qy + qz * qw);
        g_Rmat[2] = 2.0f * (qx * qz - qy * qw);
        g_Rmat[3] = 2.0f * (qx * qy - qz * qw);
        g_Rmat[4] = 1.0f - 2.0f * (qx * qx + qz * qz);
        g_Rmat[5] = 2.0f * (qy * qz + qx * qw);
        g_Rmat[6] = 2.0f * (qx * qz + qy * qw);
        g_Rmat[7] = 2.0f * (qy * qz - qx * qw);
        g_Rmat[8] = 1.0f - 2.0f * (qx * qx + qy * qy);
        g_tb[0] = tt[4]; g_tb[1] = tt[5]; g_tb[2] = tt[6];
    }
}

__global__ void k_rigid_out(const float* __restrict__ state, float* __restrict__ out) {
    int i = blockIdx.x * 256 + threadIdx.x;
    if (i >= RIGN) return;
    float c0 = g_cent[0], c1 = g_cent[1], c2 = g_cent[2];
    float p0x = state[i * 6], p0y = state[i * 6 + 1], p0z = state[i * 6 + 2];
    float dx = p0x - c0, dy = p0y - c1, dz = p0z - c2;
    float p1x = dx * g_Rmat[0] + dy * g_Rmat[3] + dz * g_Rmat[6] + g_tb[0] + c0;
    float p1y = dx * g_Rmat[1] + dy * g_Rmat[4] + dz * g_Rmat[7] + g_tb[1] + c1;
    float p1z = dx * g_Rmat[2] + dy * g_Rmat[5] + dz * g_Rmat[8] + g_tb[2] + c2;
    out[i * 3] = (p1x - p0x) * DT_INV;
    out[i * 3 + 1] = (p1y - p0y) * DT_INV;
    out[i * 3 + 2] = (p1z - p0z) * DT_INV;
}

// ---------------- fluid predictor: 128 -> 128 -> 128 -> 3 ----------------
__global__ void __launch_bounds__(256) k_fluid(const float* __restrict__ eff,
                                               const float* __restrict__ fb0,
                                               const float* __restrict__ fb1,
                                               const float* __restrict__ fw2,
                                               const float* __restrict__ fb2,
                                               float* __restrict__ out) {
    extern __shared__ float sm_[];
    float* sX = sm_;
    float* sW = sm_ + XFLOATS;
    int t = threadIdx.x;
    s_copy(sX, eff + (size_t)(32 + blockIdx.x) * 16384);
    w_copy(sW, g_bFl0, 16);
    __syncthreads();
    float acc[2][8][4];
    acc_zero(acc);
    mma_layer(sX, sW, 16, acc);
    __syncthreads();
    epi_x<1>(sX, acc, fb0);
    w_copy(sW, g_bFl1, 16);
    __syncthreads();
    acc_zero(acc);
    mma_layer(sX, sW, 16, acc);
    __syncthreads();
    epi_x<0>(sX, acc, fb1);
    __syncthreads();
    {
        int row = t & 127, grp = t >> 7;
        int p = RIGN + blockIdx.x * 128 + row;
        const float* xr = sX + row * PX;
        for (int ch = grp; ch < 3; ch += 2) {
            float o = __ldg(fb2 + ch);
            const float* wr = fw2 + ch * 128;
            for (int k = 0; k < 128; ++k) o = fmaf(__ldg(wr + k), xr[k], o);
            out[(size_t)p * 3 + ch] = o;
        }
    }
}

// ---------------- launch ----------------
extern "C" void kernel_launch(void* const* d_in, const int* in_sizes, int n_in,
                              void* d_out, int out_size) {
    const float* state = (const float*)d_in[0];
    const float* attr = (const float*)d_in[1];
    const float* Ra = (const float*)d_in[2];
    const int* recv = (const int*)d_in[3];
    const int* send = (const int*)d_in[4];
    const float* pe_w0 = (const float*)d_in[5];
    const float* pe_b0 = (const float*)d_in[6];
    const float* pe_w1 = (const float*)d_in[7];
    const float* pe_b1 = (const float*)d_in[8];
    const float* re_w0 = (const float*)d_in[9];
    const float* re_b0 = (const float*)d_in[10];
    const float* re_w1 = (const float*)d_in[11];
    const float* re_b1 = (const float*)d_in[12];
    const float* re_w2 = (const float*)d_in[13];
    const float* re_b2 = (const float*)d_in[14];
    const float* rp_w = (const float*)d_in[15];
    const float* rp_b = (const float*)d_in[16];
    const float* pp_w = (const float*)d_in[17];
    const float* pp_b = (const float*)d_in[18];
    const float* rg_w0 = (const float*)d_in[19];
    const float* rg_b0 = (const float*)d_in[20];
    const float* rg_w1 = (const float*)d_in[21];
    const float* rg_b1 = (const float*)d_in[22];
    const float* rg_w2 = (const float*)d_in[23];
    const float* rg_b2 = (const float*)d_in[24];
    const float* fl_w0 = (const float*)d_in[25];
    const float* fl_b0 = (const float*)d_in[26];
    const float* fl_w1 = (const float*)d_in[27];
    const float* fl_b1 = (const float*)d_in[28];
    const float* fl_w2 = (const float*)d_in[29];
    const float* fl_b2 = (const float*)d_in[30];
    float* out = (float*)d_out;

    cudaFuncSetAttribute(k_pe, cudaFuncAttributeMaxDynamicSharedMemorySize, SMEMSZ);
    cudaFuncSetAttribute(k_rel, cudaFuncAttributeMaxDynamicSharedMemorySize, SMEMSZ);
    cudaFuncSetAttribute(k_prop, cudaFuncAttributeMaxDynamicSharedMemorySize, SMEMSZ);
    cudaFuncSetAttribute(k_pupdate, cudaFuncAttributeMaxDynamicSharedMemorySize, SMEMSZ);
    cudaFuncSetAttribute(k_fluid, cudaFuncAttributeMaxDynamicSharedMemorySize, SMEMSZ);

    float *aggp, *pooledp, *eff1p, *eff2p;
    cudaGetSymbolAddress((void**)&aggp, g_agg);
    cudaGetSymbolAddress((void**)&pooledp, g_pooled);
    cudaGetSymbolAddress((void**)&eff1p, g_eff1);
    cudaGetSymbolAddress((void**)&eff2p, g_eff2);

    k_mkblob<<<168, 256>>>(pe_w0, pe_w1, re_w0, re_w1, re_w2, rp_w, pp_w, fl_w0, fl_w1);
    k_centroid<<<1, 256>>>(state);
    k_pe<<<NP / 128, 256, SMEMSZ>>>(state, attr, pe_b0, pe_b1);
    k_rel<<<NE / 128, 256, SMEMSZ>>>(state, attr, Ra, recv, send, re_b0, re_b1, re_b2);

    // propagation step 1 (effect == 0 -> rel chunk only)
    cudaMemsetAsync(aggp, 0, (size_t)NP * 128 * sizeof(float));
    k_prop<<<NE / 128, 256, SMEMSZ>>>(recv, send, eff1p, rp_b, 0);
    k_pupdate<<<NP / 128, 256, SMEMSZ>>>(pp_b, eff1p);

    // propagation step 2
    cudaMemsetAsync(aggp, 0, (size_t)NP * 128 * sizeof(float));
    k_prop<<<NE / 128, 256, SMEMSZ>>>(recv, send, eff1p, rp_b, 1);
    k_pupdate<<<NP / 128, 256, SMEMSZ>>>(pp_b, eff2p);

    // rigid branch
    cudaMemsetAsync(pooledp, 0, 128 * sizeof(float));
    k_pool<<<RIGN / 128, 128>>>(eff2p);
    k_rigid_mlp<<<1, 128>>>(rg_w0, rg_b0, rg_w1, rg_b1, rg_w2, rg_b2);
    k_rigid_out<<<RIGN / 256, 256>>>(state, out);

    // fluid branch
    k_fluid<<<(NP - RIGN) / 128, 256, SMEMSZ>>>(eff2p, fl_b0, fl_b1, fl_w2, fl_b2, out);
}

// round 11
// speedup vs baseline: 3.7596x; 1.8610x over previous
#include <cuda_runtime.h>
#include <cstddef>
#include <cstdint>

#define NP 65536
#define NE 524288
#define RIGN 4096
#define DT_INV 60.0f
#define PX 132                       // X pitch in floats
#define XFLOATS (128 * PX)           // 16896 floats
#define CHUNKF 1280                  // floats per k-chunk in a weight blob
#define SMEMSZ (XFLOATS * 4)         // 67584 bytes -> 2 CTAs/SM

// ---------------- device globals (no allocation allowed) ----------------
__device__ float g_cent[6];
__device__ float g_pooled[128];
__device__ float g_Rmat[9];
__device__ float g_tb[3];
// row-major activation buffers
__device__ __align__(16) float g_pe[(size_t)NP * 128];
__device__ __align__(16) float g_rel[(size_t)NE * 128];
__device__ __align__(16) float g_agg[(size_t)NP * 128];
__device__ __align__(16) float g_eff1[(size_t)NP * 128];
__device__ __align__(16) float g_eff2[(size_t)NP * 128];
// pre-permuted per-thread weight blobs: [kc][h][lane][20] (16 used + 4 pad)
__device__ __align__(16) float g_bPe0[4 * CHUNKF];
__device__ __align__(16) float g_bPe1[16 * CHUNKF];
__device__ __align__(16) float g_bRe0[4 * CHUNKF];
__device__ __align__(16) float g_bRe1[16 * CHUNKF];
__device__ __align__(16) float g_bRe2[16 * CHUNKF];
__device__ __align__(16) float g_bRp[48 * CHUNKF];
__device__ __align__(16) float g_bPp[32 * CHUNKF];
__device__ __align__(16) float g_bFl0[16 * CHUNKF];
__device__ __align__(16) float g_bFl1[16 * CHUNKF];

// ---------------- helpers ----------------
__device__ __forceinline__ float totf32(float x) {
    uint32_t u;
    asm("cvt.rna.tf32.f32 %0, %1;" : "=r"(u) : "f"(x));
    return __uint_as_float(u);
}
__device__ __forceinline__ void mma_tf32(float* d, uint32_t a0, uint32_t a1, uint32_t a2,
                                         uint32_t a3, uint32_t b0, uint32_t b1) {
    asm volatile(
        "mma.sync.aligned.m16n8k8.row.col.f32.tf32.tf32.f32 "
        "{%0,%1,%2,%3}, {%4,%5,%6,%7}, {%8,%9}, {%0,%1,%2,%3};"
        : "+f"(d[0]), "+f"(d[1]), "+f"(d[2]), "+f"(d[3])
        : "r"(a0), "r"(a1), "r"(a2), "r"(a3), "r"(b0), "r"(b1));
}
__device__ __forceinline__ void red2(float* p, float v0, float v1) {
    asm volatile("red.global.add.v2.f32 [%0], {%1, %2};" :: "l"(p), "f"(v0), "f"(v1) : "memory");
}

// core: D[128,128] += X[128,K] * W^T[K,128]; 8 warps, warp tile 32 rows x 64 feats.
// B fragments stream straight from the global blob (L1/L2-resident) with a
// one-chunk register prefetch; X fragments come from smem.
__device__ __forceinline__ void mma_layer(const float* sX, const float* __restrict__ gW,
                                          int nchunks, float acc[2][8][4]) {
    int lane = threadIdx.x & 31, warp = threadIdx.x >> 5;
    int rb = (warp & 3) * 32, h = warp >> 2;
    int g = lane >> 2, tig = lane & 3;
    const float* x0 = sX + (rb + g) * PX + tig;
    const float4* wp = (const float4*)(gW + (h * 32 + lane) * 20);
    float4 cur[4];
#pragma unroll
    for (int q = 0; q < 4; ++q) cur[q] = __ldg(wp + q);
    for (int kc = 0; kc < nchunks; ++kc) {
        int kn = (kc + 1 < nchunks) ? kc + 1 : kc;
        const float4* wn = wp + (size_t)kn * (CHUNKF / 4);
        float4 nxt[4];
#pragma unroll
        for (int q = 0; q < 4; ++q) nxt[q] = __ldg(wn + q);
        uint32_t A[2][4];
#pragma unroll
        for (int mt = 0; mt < 2; ++mt) {
            const float* xp = x0 + mt * 16 * PX + kc * 8;
            A[mt][0] = __float_as_uint(xp[0]);
            A[mt][1] = __float_as_uint(xp[8 * PX]);
            A[mt][2] = __float_as_uint(xp[4]);
            A[mt][3] = __float_as_uint(xp[8 * PX + 4]);
        }
#pragma unroll
        for (int j = 0; j < 8; ++j) {
            float4 q = cur[j >> 1];
            uint32_t b0 = __float_as_uint((j & 1) ? q.z : q.x);
            uint32_t b1 = __float_as_uint((j & 1) ? q.w : q.y);
#pragma unroll
            for (int mt = 0; mt < 2; ++mt)
                mma_tf32(acc[mt][j], A[mt][0], A[mt][1], A[mt][2], A[mt][3], b0, b1);
        }
#pragma unroll
        for (int q = 0; q < 4; ++q) cur[q] = nxt[q];
    }
}
__device__ __forceinline__ void acc_zero(float acc[2][8][4]) {
#pragma unroll
    for (int mt = 0; mt < 2; ++mt)
#pragma unroll
        for (int j = 0; j < 8; ++j)
#pragma unroll
            for (int q = 0; q < 4; ++q) acc[mt][j][q] = 0.0f;
}
// bias + relu (+tf32 cvt) -> X in place
template <int CVT>
__device__ __forceinline__ void epi_x(float* sX, float acc[2][8][4],
                                      const float* __restrict__ bias) {
    int lane = threadIdx.x & 31, warp = threadIdx.x >> 5;
    int rb = (warp & 3) * 32, h = warp >> 2;
    int g = lane >> 2, tig = lane & 3;
#pragma unroll
    for (int j = 0; j < 8; ++j) {
        int c = h * 64 + j * 8 + tig * 2;
        float bx = __ldg(bias + c), by = __ldg(bias + c + 1);
#pragma unroll
        for (int mt = 0; mt < 2; ++mt) {
            int r = rb + mt * 16 + g;
            float v0 = fmaxf(acc[mt][j][0] + bx, 0.f);
            float v1 = fmaxf(acc[mt][j][1] + by, 0.f);
            float v2 = fmaxf(acc[mt][j][2] + bx, 0.f);
            float v3 = fmaxf(acc[mt][j][3] + by, 0.f);
            if (CVT) { v0 = totf32(v0); v1 = totf32(v1); v2 = totf32(v2); v3 = totf32(v3); }
            *(float2*)(sX + r * PX + c) = make_float2(v0, v1);
            *(float2*)(sX + (r + 8) * PX + c) = make_float2(v2, v3);
        }
    }
}
// bias + relu -> vectorized atomic scatter into g_agg[recv]
__device__ __forceinline__ void epi_scatter(const int* __restrict__ recv, int e0,
                                            float acc[2][8][4], const float* __restrict__ bias) {
    int lane = threadIdx.x & 31, warp = threadIdx.x >> 5;
    int rb = (warp & 3) * 32, h = warp >> 2;
    int g = lane >> 2, tig = lane & 3;
#pragma unroll
    for (int mt = 0; mt < 2; ++mt) {
        int ra = rb + mt * 16 + g;
        int va = __ldg(recv + e0 + ra), vb = __ldg(recv + e0 + ra + 8);
        float* pa = g_agg + (size_t)va * 128;
        float* pb = g_agg + (size_t)vb * 128;
#pragma unroll
        for (int j = 0; j < 8; ++j) {
            int c = h * 64 + j * 8 + tig * 2;
            float bx = __ldg(bias + c), by = __ldg(bias + c + 1);
            red2(pa + c, fmaxf(acc[mt][j][0] + bx, 0.f), fmaxf(acc[mt][j][1] + by, 0.f));
            red2(pb + c, fmaxf(acc[mt][j][2] + bx, 0.f), fmaxf(acc[mt][j][3] + by, 0.f));
        }
    }
}
// staging copies (256 threads)
__device__ __forceinline__ void s_copy(float* sX, const float* __restrict__ g) {
    for (int i = threadIdx.x; i < 4096; i += 256) {
        int r = i >> 5, c4 = i & 31;
        ((float4*)sX)[r * 33 + c4] = ((const float4*)g)[i];
    }
}
__device__ __forceinline__ void s_copy_cvt(float* sX, const float* __restrict__ g) {
    for (int i = threadIdx.x; i < 4096; i += 256) {
        int r = i >> 5, c4 = i & 31;
        float4 v = ((const float4*)g)[i];
        v.x = totf32(v.x); v.y = totf32(v.y); v.z = totf32(v.z); v.w = totf32(v.w);
        ((float4*)sX)[r * 33 + c4] = v;
    }
}
__device__ __forceinline__ void copy_out(float* __restrict__ g, const float* sX) {
    for (int i = threadIdx.x; i < 4096; i += 256) {
        int r = i >> 5, c4 = i & 31;
        ((float4*)g)[i] = ((const float4*)sX)[r * 33 + c4];
    }
}
// gather 128 rows src[idx[e0+r]] (row-major [p][128]) -> X
__device__ __forceinline__ void s_gather(float* sX, const float* __restrict__ src,
                                         const int* __restrict__ idx, int e0) {
    int row = threadIdx.x & 127, kq = threadIdx.x >> 7;
    int p = __ldg(idx + e0 + row);
    const float4* s4 = (const float4*)(src + (size_t)p * 128 + kq * 64);
    float4* d4 = (float4*)(sX + row * PX + kq * 64);
#pragma unroll
    for (int q = 0; q < 16; ++q) d4[q] = s4[q];
}

// ---------------- setup: weight blobs ----------------
__global__ void k_mkblob(const float* __restrict__ pe_w0, const float* __restrict__ pe_w1,
                         const float* __restrict__ re_w0, const float* __restrict__ re_w1,
                         const float* __restrict__ re_w2, const float* __restrict__ rp_w,
                         const float* __restrict__ pp_w, const float* __restrict__ fl_w0,
                         const float* __restrict__ fl_w1) {
    int b = blockIdx.x;
    const float* src; float* blob;
    int Ktot, Kval, kc, base;
    if (b < 4)         { src = pe_w0; blob = g_bPe0; Ktot = 15;  Kval = 15;  base = 0; }
    else if (b < 20)   { src = pe_w1; blob = g_bPe1; Ktot = 128; Kval = 128; base = 4; }
    else if (b < 24)   { src = re_w0; blob = g_bRe0; Ktot = 31;  Kval = 31;  base = 20; }
    else if (b < 40)   { src = re_w1; blob = g_bRe1; Ktot = 128; Kval = 128; base = 24; }
    else if (b < 56)   { src = re_w2; blob = g_bRe2; Ktot = 128; Kval = 128; base = 40; }
    else if (b < 104)  { src = rp_w;  blob = g_bRp;  Ktot = 384; Kval = 384; base = 56; }
    else if (b < 136)  { src = pp_w;  blob = g_bPp;  Ktot = 256; Kval = 256; base = 104; }
    else if (b < 152)  { src = fl_w0; blob = g_bFl0; Ktot = 128; Kval = 128; base = 136; }
    else               { src = fl_w1; blob = g_bFl1; Ktot = 128; Kval = 128; base = 152; }
    kc = b - base;
    for (int i = threadIdx.x; i < CHUNKF; i += 256) {
        int h = i / 640, rr = i % 640, lane = rr / 20, q = rr % 20;
        float v = 0.0f;
        if (q < 16) {
            int j = q >> 1, s = q & 1;
            int tig = lane & 3, g = lane >> 2;
            int k = kc * 8 + tig + 4 * s;
            int n = h * 64 + j * 8 + g;
            if (k < Kval) v = totf32(src[n * Ktot + k]);
        }
        blob[kc * CHUNKF + i] = v;
    }
}

__global__ void k_centroid(const float* __restrict__ state) {
    __shared__ float red[256];
    float s[6] = {0, 0, 0, 0, 0, 0};
    for (int r = threadIdx.x; r < RIGN; r += 256)
#pragma unroll
        for (int c = 0; c < 6; ++c) s[c] += state[r * 6 + c];
#pragma unroll
    for (int c = 0; c < 6; ++c) {
        red[threadIdx.x] = s[c];
        __syncthreads();
        for (int off = 128; off > 0; off >>= 1) {
            if (threadIdx.x < off) red[threadIdx.x] += red[threadIdx.x + off];
            __syncthreads();
        }
        if (threadIdx.x == 0) g_cent[c] = red[0] * (1.0f / RIGN);
        __syncthreads();
    }
}

// ---------------- particle encoder: 15(pad32) -> 128 -> 128 ----------------
__global__ void __launch_bounds__(256, 2) k_pe(const float* __restrict__ state,
                                               const float* __restrict__ attr,
                                               const float* __restrict__ b0,
                                               const float* __restrict__ b1) {
    extern __shared__ float sm_[];
    float* sX = sm_;
    int t = threadIdx.x;
    int p0 = blockIdx.x * 128;
    {
        int row = t & 127, grp = t >> 7;
        int p = p0 + row;
        float* xr = sX + row * PX;
        if (grp == 0) {
#pragma unroll
            for (int c = 0; c < 3; ++c) xr[c] = totf32(attr[p * 3 + c]);
#pragma unroll
            for (int c = 0; c < 6; ++c) xr[9 + c] = totf32(state[p * 6 + c]);
        } else {
#pragma unroll
            for (int c = 0; c < 6; ++c) {
                float s = state[p * 6 + c];
                xr[3 + c] = (p < RIGN) ? totf32(s - g_cent[c]) : 0.0f;
            }
            for (int c = 15; c < 32; ++c) xr[c] = 0.0f;
        }
    }
    __syncthreads();
    float acc[2][8][4];
    acc_zero(acc);
    mma_layer(sX, g_bPe0, 4, acc);
    __syncthreads();
    epi_x<1>(sX, acc, b0);
    __syncthreads();
    acc_zero(acc);
    mma_layer(sX, g_bPe1, 16, acc);
    __syncthreads();
    epi_x<1>(sX, acc, b1);
    __syncthreads();
    copy_out(g_pe + (size_t)blockIdx.x * 16384, sX);
}

// ---------------- relation encoder: 31(pad32) -> 128 -> 128 -> 128 ----------------
__global__ void __launch_bounds__(256, 2) k_rel(const float* __restrict__ state,
                                                const float* __restrict__ attr,
                                                const float* __restrict__ Ra,
                                                const int* __restrict__ recv,
                                                const int* __restrict__ send,
                                                const float* __restrict__ b0,
                                                const float* __restrict__ b1,
                                                const float* __restrict__ b2) {
    extern __shared__ float sm_[];
    float* sX = sm_;
    int t = threadIdx.x;
    int e0 = blockIdx.x * 128;
    {
        int row = t & 127, grp = t >> 7;
        int e = e0 + row;
        float* xr = sX + row * PX;
        if (grp == 0) {
            int rv = __ldg(recv + e);
#pragma unroll
            for (int c = 0; c < 3; ++c) xr[c] = totf32(attr[rv * 3 + c]);
#pragma unroll
            for (int c = 0; c < 6; ++c) {
                float s = state[rv * 6 + c];
                xr[3 + c] = (rv < RIGN) ? totf32(s - g_cent[c]) : 0.0f;
                xr[18 + c] = totf32(s);
            }
        } else {
            int sd = __ldg(send + e);
#pragma unroll
            for (int c = 0; c < 3; ++c) xr[9 + c] = totf32(attr[sd * 3 + c]);
#pragma unroll
            for (int c = 0; c < 6; ++c) {
                float s = state[sd * 6 + c];
                xr[12 + c] = (sd < RIGN) ? totf32(s - g_cent[c]) : 0.0f;
                xr[24 + c] = totf32(s);
            }
            xr[30] = totf32(Ra[e]);
            xr[31] = 0.0f;
        }
    }
    __syncthreads();
    float acc[2][8][4];
    acc_zero(acc);
    mma_layer(sX, g_bRe0, 4, acc);
    __syncthreads();
    epi_x<1>(sX, acc, b0);
    __syncthreads();
    acc_zero(acc);
    mma_layer(sX, g_bRe1, 16, acc);
    __syncthreads();
    epi_x<1>(sX, acc, b1);
    __syncthreads();
    acc_zero(acc);
    mma_layer(sX, g_bRe2, 16, acc);
    __syncthreads();
    epi_x<1>(sX, acc, b2);
    __syncthreads();
    copy_out(g_rel + (size_t)blockIdx.x * 16384, sX);
}

// ---------------- propagation edge pass ----------------
__global__ void __launch_bounds__(256, 2) k_prop(const int* __restrict__ recv,
                                                 const int* __restrict__ send,
                                                 const float* __restrict__ eff,
                                                 const float* __restrict__ rp_b, int use_eff) {
    extern __shared__ float sm_[];
    float* sX = sm_;
    int e0 = blockIdx.x * 128;
    s_copy(sX, g_rel + (size_t)blockIdx.x * 16384);
    __syncthreads();
    float acc[2][8][4];
    acc_zero(acc);
    mma_layer(sX, g_bRp, 16, acc);
    if (use_eff) {
        __syncthreads();
        s_gather(sX, eff, recv, e0);
        __syncthreads();
        mma_layer(sX, g_bRp + 16 * CHUNKF, 16, acc);
        __syncthreads();
        s_gather(sX, eff, send, e0);
        __syncthreads();
        mma_layer(sX, g_bRp + 32 * CHUNKF, 16, acc);
    }
    epi_scatter(recv, e0, acc, rp_b);
}

// ---------------- particle update: [pe, agg] -> 128 ----------------
__global__ void __launch_bounds__(256, 2) k_pupdate(const float* __restrict__ pp_b,
                                                    float* __restrict__ effOut) {
    extern __shared__ float sm_[];
    float* sX = sm_;
    s_copy(sX, g_pe + (size_t)blockIdx.x * 16384);
    __syncthreads();
    float acc[2][8][4];
    acc_zero(acc);
    mma_layer(sX, g_bPp, 16, acc);
    __syncthreads();
    s_copy_cvt(sX, g_agg + (size_t)blockIdx.x * 16384);
    __syncthreads();
    mma_layer(sX, g_bPp + 16 * CHUNKF, 16, acc);
    __syncthreads();
    epi_x<1>(sX, acc, pp_b);
    __syncthreads();
    copy_out(effOut + (size_t)blockIdx.x * 16384, sX);
}

// ---------------- rigid pooling + small MLP + rigid output ----------------
__global__ void k_pool(const float* __restrict__ eff) {
    int f = threadIdx.x;  // 128
    int r0 = blockIdx.x * 128;
    float s = 0.0f;
    for (int r = 0; r < 128; ++r) s += eff[(size_t)(r0 + r) * 128 + f];
    atomicAdd(&g_pooled[f], s);
}

__global__ void k_rigid_mlp(const float* __restrict__ w0, const float* __restrict__ b0,
                            const float* __restrict__ w1, const float* __restrict__ b1,
                            const float* __restrict__ w2, const float* __restrict__ b2) {
    __shared__ float pin[128], h0[128], h1[128], tt[7];
    int t = threadIdx.x;  // 128
    pin[t] = g_pooled[t] * (1.0f / RIGN);
    __syncthreads();
    float s = b0[t];
    for (int k = 0; k < 128; ++k) s = fmaf(w0[t * 128 + k], pin[k], s);
    h0[t] = fmaxf(s, 0.0f);
    __syncthreads();
    s = b1[t];
    for (int k = 0; k < 128; ++k) s = fmaf(w1[t * 128 + k], h0[k], s);
    h1[t] = fmaxf(s, 0.0f);
    __syncthreads();
    if (t < 7) {
        s = b2[t];
        for (int k = 0; k < 128; ++k) s = fmaf(w2[t * 128 + k], h1[k], s);
        tt[t] = s;
    }
    __syncthreads();
    if (t == 0) {
        float qw = tt[0], qx = tt[1], qy = tt[2], qz = tt[3];
        float inv = rsqrtf(qw * qw + qx * qx + qy * qy + qz * qz);
        qw *= inv; qx *= inv; qy *= inv; qz *= inv;
        g_Rmat[0] = 1.0f - 2.0f * (qy * qy + qz * qz);
        g_Rmat[1] = 2.0f * (qx * qy + qz * qw);
        g_Rmat[2] = 2.0f * (qx * qz - qy * qw);
        g_Rmat[3] = 2.0f * (qx * qy - qz * qw);
        g_Rmat[4] = 1.0f - 2.0f * (qx * qx + qz * qz);
        g_Rmat[5] = 2.0f * (qy * qz + qx * qw);
        g_Rmat[6] = 2.0f * (qx * qz + qy * qw);
        g_Rmat[7] = 2.0f * (qy * qz - qx * qw);
        g_Rmat[8] = 1.0f - 2.0f * (qx * qx + qy * qy);
        g_tb[0] = tt[4]; g_tb[1] = tt[5]; g_tb[2] = tt[6];
    }
}

__global__ void k_rigid_out(const float* __restrict__ state, float* __restrict__ out) {
    int i = blockIdx.x * 256 + threadIdx.x;
    if (i >= RIGN) return;
    float c0 = g_cent[0], c1 = g_cent[1], c2 = g_cent[2];
    float p0x = state[i * 6], p0y = state[i * 6 + 1], p0z = state[i * 6 + 2];
    float dx = p0x - c0, dy = p0y - c1, dz = p0z - c2;
    float p1x = dx * g_Rmat[0] + dy * g_Rmat[3] + dz * g_Rmat[6] + g_tb[0] + c0;
    float p1y = dx * g_Rmat[1] + dy * g_Rmat[4] + dz * g_Rmat[7] + g_tb[1] + c1;
    float p1z = dx * g_Rmat[2] + dy * g_Rmat[5] + dz * g_Rmat[8] + g_tb[2] + c2;
    out[i * 3] = (p1x - p0x) * DT_INV;
    out[i * 3 + 1] = (p1y - p0y) * DT_INV;
    out[i * 3 + 2] = (p1z - p0z) * DT_INV;
}

// ---------------- fluid predictor: 128 -> 128 -> 128 -> 3 ----------------
__global__ void __launch_bounds__(256, 2) k_fluid(const float* __restrict__ eff,
                                                  const float* __restrict__ fb0,
                                                  const float* __restrict__ fb1,
                                                  const float* __restrict__ fw2,
                                                  const float* __restrict__ fb2,
                                                  float* __restrict__ out) {
    extern __shared__ float sm_[];
    float* sX = sm_;
    int t = threadIdx.x;
    s_copy(sX, eff + (size_t)(32 + blockIdx.x) * 16384);
    __syncthreads();
    float acc[2][8][4];
    acc_zero(acc);
    mma_layer(sX, g_bFl0, 16, acc);
    __syncthreads();
    epi_x<1>(sX, acc, fb0);
    __syncthreads();
    acc_zero(acc);
    mma_layer(sX, g_bFl1, 16, acc);
    __syncthreads();
    epi_x<0>(sX, acc, fb1);
    __syncthreads();
    {
        int row = t & 127, grp = t >> 7;
        int p = RIGN + blockIdx.x * 128 + row;
        const float* xr = sX + row * PX;
        for (int ch = grp; ch < 3; ch += 2) {
            float o = __ldg(fb2 + ch);
            const float* wr = fw2 + ch * 128;
            for (int k = 0; k < 128; ++k) o = fmaf(__ldg(wr + k), xr[k], o);
            out[(size_t)p * 3 + ch] = o;
        }
    }
}

// ---------------- launch ----------------
extern "C" void kernel_launch(void* const* d_in, const int* in_sizes, int n_in,
                              void* d_out, int out_size) {
    const float* state = (const float*)d_in[0];
    const float* attr = (const float*)d_in[1];
    const float* Ra = (const float*)d_in[2];
    const int* recv = (const int*)d_in[3];
    const int* send = (const int*)d_in[4];
    const float* pe_w0 = (const float*)d_in[5];
    const float* pe_b0 = (const float*)d_in[6];
    const float* pe_w1 = (const float*)d_in[7];
    const float* pe_b1 = (const float*)d_in[8];
    const float* re_w0 = (const float*)d_in[9];
    const float* re_b0 = (const float*)d_in[10];
    const float* re_w1 = (const float*)d_in[11];
    const float* re_b1 = (const float*)d_in[12];
    const float* re_w2 = (const float*)d_in[13];
    const float* re_b2 = (const float*)d_in[14];
    const float* rp_w = (const float*)d_in[15];
    const float* rp_b = (const float*)d_in[16];
    const float* pp_w = (const float*)d_in[17];
    const float* pp_b = (const float*)d_in[18];
    const float* rg_w0 = (const float*)d_in[19];
    const float* rg_b0 = (const float*)d_in[20];
    const float* rg_w1 = (const float*)d_in[21];
    const float* rg_b1 = (const float*)d_in[22];
    const float* rg_w2 = (const float*)d_in[23];
    const float* rg_b2 = (const float*)d_in[24];
    const float* fl_w0 = (const float*)d_in[25];
    const float* fl_b0 = (const float*)d_in[26];
    const float* fl_w1 = (const float*)d_in[27];
    const float* fl_b1 = (const float*)d_in[28];
    const float* fl_w2 = (const float*)d_in[29];
    const float* fl_b2 = (const float*)d_in[30];
    float* out = (float*)d_out;

    cudaFuncSetAttribute(k_pe, cudaFuncAttributeMaxDynamicSharedMemorySize, SMEMSZ);
    cudaFuncSetAttribute(k_rel, cudaFuncAttributeMaxDynamicSharedMemorySize, SMEMSZ);
    cudaFuncSetAttribute(k_prop, cudaFuncAttributeMaxDynamicSharedMemorySize, SMEMSZ);
    cudaFuncSetAttribute(k_pupdate, cudaFuncAttributeMaxDynamicSharedMemorySize, SMEMSZ);
    cudaFuncSetAttribute(k_fluid, cudaFuncAttributeMaxDynamicSharedMemorySize, SMEMSZ);

    float *aggp, *pooledp, *eff1p, *eff2p;
    cudaGetSymbolAddress((void**)&aggp, g_agg);
    cudaGetSymbolAddress((void**)&pooledp, g_pooled);
    cudaGetSymbolAddress((void**)&eff1p, g_eff1);
    cudaGetSymbolAddress((void**)&eff2p, g_eff2);

    k_mkblob<<<168, 256>>>(pe_w0, pe_w1, re_w0, re_w1, re_w2, rp_w, pp_w, fl_w0, fl_w1);
    k_centroid<<<1, 256>>>(state);
    k_pe<<<NP / 128, 256, SMEMSZ>>>(state, attr, pe_b0, pe_b1);
    k_rel<<<NE / 128, 256, SMEMSZ>>>(state, attr, Ra, recv, send, re_b0, re_b1, re_b2);

    // propagation step 1 (effect == 0 -> rel chunk only)
    cudaMemsetAsync(aggp, 0, (size_t)NP * 128 * sizeof(float));
    k_prop<<<NE / 128, 256, SMEMSZ>>>(recv, send, eff1p, rp_b, 0);
    k_pupdate<<<NP / 128, 256, SMEMSZ>>>(pp_b, eff1p);

    // propagation step 2
    cudaMemsetAsync(aggp, 0, (size_t)NP * 128 * sizeof(float));
    k_prop<<<NE / 128, 256, SMEMSZ>>>(recv, send, eff1p, rp_b, 1);
    k_pupdate<<<NP / 128, 256, SMEMSZ>>>(pp_b, eff2p);

    // rigid branch
    cudaMemsetAsync(pooledp, 0, 128 * sizeof(float));
    k_pool<<<RIGN / 128, 128>>>(eff2p);
    k_rigid_mlp<<<1, 128>>>(rg_w0, rg_b0, rg_w1, rg_b1, rg_w2, rg_b2);
    k_rigid_out<<<RIGN / 256, 256>>>(state, out);

    // fluid branch
    k_fluid<<<(NP - RIGN) / 128, 256, SMEMSZ>>>(eff2p, fl_b0, fl_b1, fl_w2, fl_b2, out);
}

// round 12
// speedup vs baseline: 5.1923x; 1.3811x over previous
#include <cuda_runtime.h>
#include <cuda_fp16.h>
#include <cstddef>
#include <cstdint>

#define NP 65536
#define NE 524288
#define RIGN 4096
#define DT_INV 60.0f
#define PXH 136                       // X pitch in halves (= 68 words, conflict-free)
#define CHUNKH 2048                   // halves per K16 weight chunk (2 h * 32 lanes * 32)
#define SMEMSZ (128 * PXH * 2)        // 34816 bytes

// ---------------- device globals (no allocation allowed) ----------------
__device__ float g_cent[6];
__device__ float g_pooled[128];
__device__ float g_Rmat[9];
__device__ float g_tb[3];
// fp16 row-major activation buffers [p][128]
__device__ __align__(16) __half g_pe[(size_t)NP * 128];
__device__ __align__(16) __half g_rel[(size_t)NE * 128];
__device__ __align__(16) __half g_eff1[(size_t)NP * 128];
__device__ __align__(16) __half g_eff2[(size_t)NP * 128];
// f32 aggregation buffer (atomics)
__device__ __align__(16) float g_agg[(size_t)NP * 128];
// fp16 weight blobs, m16n8k16 B-fragment order: [kc][h][lane][32 halves]
__device__ __align__(16) __half g_bPe0[2 * CHUNKH];
__device__ __align__(16) __half g_bPe1[8 * CHUNKH];
__device__ __align__(16) __half g_bRe0[2 * CHUNKH];
__device__ __align__(16) __half g_bRe1[8 * CHUNKH];
__device__ __align__(16) __half g_bRe2[8 * CHUNKH];
__device__ __align__(16) __half g_bRp[24 * CHUNKH];
__device__ __align__(16) __half g_bPp[16 * CHUNKH];
__device__ __align__(16) __half g_bFl0[8 * CHUNKH];
__device__ __align__(16) __half g_bFl1[8 * CHUNKH];

// ---------------- helpers ----------------
__device__ __forceinline__ void mma_f16(float* d, uint32_t a0, uint32_t a1, uint32_t a2,
                                        uint32_t a3, uint32_t b0, uint32_t b1) {
    asm volatile(
        "mma.sync.aligned.m16n8k16.row.col.f32.f16.f16.f32 "
        "{%0,%1,%2,%3}, {%4,%5,%6,%7}, {%8,%9}, {%0,%1,%2,%3};"
        : "+f"(d[0]), "+f"(d[1]), "+f"(d[2]), "+f"(d[3])
        : "r"(a0), "r"(a1), "r"(a2), "r"(a3), "r"(b0), "r"(b1));
}
__device__ __forceinline__ void red2(float* p, float v0, float v1) {
    asm volatile("red.global.add.v2.f32 [%0], {%1, %2};" :: "l"(p), "f"(v0), "f"(v1) : "memory");
}
__device__ __forceinline__ uint32_t f4word(const float4& v, int w) {
    return (w == 0) ? __float_as_uint(v.x) : (w == 1) ? __float_as_uint(v.y)
         : (w == 2) ? __float_as_uint(v.z) : __float_as_uint(v.w);
}

// core: D[128,128] += X[128,K] * W^T[K,128]; 8 warps, warp tile 32 rows x 64 feats.
// fp16 m16n8k16; W streams from global blob with one-chunk register prefetch.
__device__ __forceinline__ void mma_layer(const __half* sX, const __half* __restrict__ gW,
                                          int nchunks, float acc[2][8][4]) {
    int lane = threadIdx.x & 31, warp = threadIdx.x >> 5;
    int rb = (warp & 3) * 32, h = warp >> 2;
    int g = lane >> 2, tig = lane & 3;
    const __half* x0 = sX + (rb + g) * PXH + tig * 2;
    const float4* wp = (const float4*)(gW + ((h * 32 + lane) * 32));
    float4 cur[4];
#pragma unroll
    for (int q = 0; q < 4; ++q) cur[q] = __ldg(wp + q);
    for (int kc = 0; kc < nchunks; ++kc) {
        int kn = (kc + 1 < nchunks) ? kc + 1 : kc;
        const float4* wn = (const float4*)((const __half*)wp + (size_t)kn * CHUNKH);
        float4 nxt[4];
#pragma unroll
        for (int q = 0; q < 4; ++q) nxt[q] = __ldg(wn + q);
        uint32_t A[2][4];
#pragma unroll
        for (int mt = 0; mt < 2; ++mt) {
            const __half* xp = x0 + mt * 16 * PXH + kc * 16;
            A[mt][0] = *(const uint32_t*)(xp);
            A[mt][1] = *(const uint32_t*)(xp + 8 * PXH);
            A[mt][2] = *(const uint32_t*)(xp + 8);
            A[mt][3] = *(const uint32_t*)(xp + 8 * PXH + 8);
        }
#pragma unroll
        for (int j = 0; j < 8; ++j) {
            uint32_t b0 = f4word(cur[j >> 1], (j & 1) * 2);
            uint32_t b1 = f4word(cur[j >> 1], (j & 1) * 2 + 1);
#pragma unroll
            for (int mt = 0; mt < 2; ++mt)
                mma_f16(acc[mt][j], A[mt][0], A[mt][1], A[mt][2], A[mt][3], b0, b1);
        }
#pragma unroll
        for (int q = 0; q < 4; ++q) cur[q] = nxt[q];
    }
}
__device__ __forceinline__ void acc_zero(float acc[2][8][4]) {
#pragma unroll
    for (int mt = 0; mt < 2; ++mt)
#pragma unroll
        for (int j = 0; j < 8; ++j)
#pragma unroll
            for (int q = 0; q < 4; ++q) acc[mt][j][q] = 0.0f;
}
// bias + relu -> fp16 X in place
__device__ __forceinline__ void epi_x(__half* sX, float acc[2][8][4],
                                      const float* __restrict__ bias) {
    int lane = threadIdx.x & 31, warp = threadIdx.x >> 5;
    int rb = (warp & 3) * 32, h = warp >> 2;
    int g = lane >> 2, tig = lane & 3;
#pragma unroll
    for (int j = 0; j < 8; ++j) {
        int c = h * 64 + j * 8 + tig * 2;
        float bx = __ldg(bias + c), by = __ldg(bias + c + 1);
#pragma unroll
        for (int mt = 0; mt < 2; ++mt) {
            int r = rb + mt * 16 + g;
            __half2 h01 = __floats2half2_rn(fmaxf(acc[mt][j][0] + bx, 0.f),
                                            fmaxf(acc[mt][j][1] + by, 0.f));
            __half2 h23 = __floats2half2_rn(fmaxf(acc[mt][j][2] + bx, 0.f),
                                            fmaxf(acc[mt][j][3] + by, 0.f));
            *(__half2*)(sX + r * PXH + c) = h01;
            *(__half2*)(sX + (r + 8) * PXH + c) = h23;
        }
    }
}
// bias + relu -> vectorized f32 atomic scatter into g_agg[recv]
__device__ __forceinline__ void epi_scatter(const int* __restrict__ recv, int e0,
                                            float acc[2][8][4], const float* __restrict__ bias) {
    int lane = threadIdx.x & 31, warp = threadIdx.x >> 5;
    int rb = (warp & 3) * 32, h = warp >> 2;
    int g = lane >> 2, tig = lane & 3;
#pragma unroll
    for (int mt = 0; mt < 2; ++mt) {
        int ra = rb + mt * 16 + g;
        int va = __ldg(recv + e0 + ra), vb = __ldg(recv + e0 + ra + 8);
        float* pa = g_agg + (size_t)va * 128;
        float* pb = g_agg + (size_t)vb * 128;
#pragma unroll
        for (int j = 0; j < 8; ++j) {
            int c = h * 64 + j * 8 + tig * 2;
            float bx = __ldg(bias + c), by = __ldg(bias + c + 1);
            red2(pa + c, fmaxf(acc[mt][j][0] + bx, 0.f), fmaxf(acc[mt][j][1] + by, 0.f));
            red2(pb + c, fmaxf(acc[mt][j][2] + bx, 0.f), fmaxf(acc[mt][j][3] + by, 0.f));
        }
    }
}
// staging copies (256 threads); global fp16 [p][128] <-> smem X fp16 pitch-136
__device__ __forceinline__ void s_copy(__half* sX, const __half* __restrict__ g) {
    for (int i = threadIdx.x; i < 2048; i += 256) {
        int r = i >> 4, q = i & 15;
        ((float4*)sX)[r * 17 + q] = ((const float4*)g)[i];
    }
}
__device__ __forceinline__ void copy_out(__half* __restrict__ g, const __half* sX) {
    for (int i = threadIdx.x; i < 2048; i += 256) {
        int r = i >> 4, q = i & 15;
        ((float4*)g)[i] = ((const float4*)sX)[r * 17 + q];
    }
}
// f32 agg -> fp16 smem X
__device__ __forceinline__ void s_copy_cvt(__half* sX, const float* __restrict__ g) {
    for (int i = threadIdx.x; i < 4096; i += 256) {
        int r = i >> 5, q = i & 31;
        float4 v = ((const float4*)g)[i];
        __half2 ha = __floats2half2_rn(v.x, v.y), hb = __floats2half2_rn(v.z, v.w);
        uint2 u;
        u.x = *(uint32_t*)&ha; u.y = *(uint32_t*)&hb;
        ((uint2*)sX)[r * 34 + q] = u;
    }
}
// gather 128 rows src[idx[e0+r]] (fp16 row-major [p][128]) -> X
__device__ __forceinline__ void s_gather(__half* sX, const __half* __restrict__ src,
                                         const int* __restrict__ idx, int e0) {
    int row = threadIdx.x & 127, kq = threadIdx.x >> 7;
    int p = __ldg(idx + e0 + row);
    const float4* s4 = (const float4*)(src + (size_t)p * 128) + kq * 8;
    float4* d4 = (float4*)(sX + row * PXH) + kq * 8;
#pragma unroll
    for (int q = 0; q < 8; ++q) d4[q] = s4[q];
}

// ---------------- setup: fp16 weight blobs in B-fragment order ----------------
__global__ void k_mkblob(const float* __restrict__ pe_w0, const float* __restrict__ pe_w1,
                         const float* __restrict__ re_w0, const float* __restrict__ re_w1,
                         const float* __restrict__ re_w2, const float* __restrict__ rp_w,
                         const float* __restrict__ pp_w, const float* __restrict__ fl_w0,
                         const float* __restrict__ fl_w1) {
    int b = blockIdx.x;
    const float* src; __half* blob;
    int Kval, base;
    if (b < 2)        { src = pe_w0; blob = g_bPe0; Kval = 15;  base = 0; }
    else if (b < 10)  { src = pe_w1; blob = g_bPe1; Kval = 128; base = 2; }
    else if (b < 12)  { src = re_w0; blob = g_bRe0; Kval = 31;  base = 10; }
    else if (b < 20)  { src = re_w1; blob = g_bRe1; Kval = 128; base = 12; }
    else if (b < 28)  { src = re_w2; blob = g_bRe2; Kval = 128; base = 20; }
    else if (b < 52)  { src = rp_w;  blob = g_bRp;  Kval = 384; base = 28; }
    else if (b < 68)  { src = pp_w;  blob = g_bPp;  Kval = 256; base = 52; }
    else if (b < 76)  { src = fl_w0; blob = g_bFl0; Kval = 128; base = 68; }
    else              { src = fl_w1; blob = g_bFl1; Kval = 128; base = 76; }
    int kc = b - base;
    for (int i = threadIdx.x; i < CHUNKH; i += 256) {
        int h = i >> 10, rr = i & 1023, lane = rr >> 5, q = rr & 31;
        int j = q >> 2, u = q & 3;
        int n = h * 64 + j * 8 + (lane >> 2);
        int k = kc * 16 + (lane & 3) * 2 + (u & 1) + ((u >> 1) << 3);
        float v = (k < Kval) ? src[n * Kval + k] : 0.0f;
        blob[kc * CHUNKH + i] = __float2half_rn(v);
    }
}

__global__ void k_centroid(const float* __restrict__ state) {
    __shared__ float red[256];
    float s[6] = {0, 0, 0, 0, 0, 0};
    for (int r = threadIdx.x; r < RIGN; r += 256)
#pragma unroll
        for (int c = 0; c < 6; ++c) s[c] += state[r * 6 + c];
#pragma unroll
    for (int c = 0; c < 6; ++c) {
        red[threadIdx.x] = s[c];
        __syncthreads();
        for (int off = 128; off > 0; off >>= 1) {
            if (threadIdx.x < off) red[threadIdx.x] += red[threadIdx.x + off];
            __syncthreads();
        }
        if (threadIdx.x == 0) g_cent[c] = red[0] * (1.0f / RIGN);
        __syncthreads();
    }
}

// ---------------- particle encoder: 15(pad32) -> 128 -> 128 ----------------
__global__ void __launch_bounds__(256, 2) k_pe(const float* __restrict__ state,
                                               const float* __restrict__ attr,
                                               const float* __restrict__ b0,
                                               const float* __restrict__ b1) {
    extern __shared__ __half sm_[];
    __half* sX = sm_;
    int t = threadIdx.x;
    int p0 = blockIdx.x * 128;
    {
        int row = t & 127, grp = t >> 7;
        int p = p0 + row;
        __half* xr = sX + row * PXH;
        if (grp == 0) {
#pragma unroll
            for (int c = 0; c < 3; ++c) xr[c] = __float2half_rn(attr[p * 3 + c]);
#pragma unroll
            for (int c = 0; c < 6; ++c) xr[9 + c] = __float2half_rn(state[p * 6 + c]);
        } else {
#pragma unroll
            for (int c = 0; c < 6; ++c) {
                float s = state[p * 6 + c];
                xr[3 + c] = (p < RIGN) ? __float2half_rn(s - g_cent[c]) : __half(0.0f);
            }
            for (int c = 15; c < 32; ++c) xr[c] = __half(0.0f);
        }
    }
    __syncthreads();
    float acc[2][8][4];
    acc_zero(acc);
    mma_layer(sX, g_bPe0, 2, acc);
    __syncthreads();
    epi_x(sX, acc, b0);
    __syncthreads();
    acc_zero(acc);
    mma_layer(sX, g_bPe1, 8, acc);
    __syncthreads();
    epi_x(sX, acc, b1);
    __syncthreads();
    copy_out(g_pe + (size_t)blockIdx.x * 16384, sX);
}

// ---------------- relation encoder: 31(pad32) -> 128 -> 128 -> 128 ----------------
__global__ void __launch_bounds__(256, 2) k_rel(const float* __restrict__ state,
                                                const float* __restrict__ attr,
                                                const float* __restrict__ Ra,
                                                const int* __restrict__ recv,
                                                const int* __restrict__ send,
                                                const float* __restrict__ b0,
                                                const float* __restrict__ b1,
                                                const float* __restrict__ b2) {
    extern __shared__ __half sm_[];
    __half* sX = sm_;
    int t = threadIdx.x;
    int e0 = blockIdx.x * 128;
    {
        int row = t & 127, grp = t >> 7;
        int e = e0 + row;
        __half* xr = sX + row * PXH;
        if (grp == 0) {
            int rv = __ldg(recv + e);
#pragma unroll
            for (int c = 0; c < 3; ++c) xr[c] = __float2half_rn(attr[rv * 3 + c]);
#pragma unroll
            for (int c = 0; c < 6; ++c) {
                float s = state[rv * 6 + c];
                xr[3 + c] = (rv < RIGN) ? __float2half_rn(s - g_cent[c]) : __half(0.0f);
                xr[18 + c] = __float2half_rn(s);
            }
        } else {
            int sd = __ldg(send + e);
#pragma unroll
            for (int c = 0; c < 3; ++c) xr[9 + c] = __float2half_rn(attr[sd * 3 + c]);
#pragma unroll
            for (int c = 0; c < 6; ++c) {
                float s = state[sd * 6 + c];
                xr[12 + c] = (sd < RIGN) ? __float2half_rn(s - g_cent[c]) : __half(0.0f);
                xr[24 + c] = __float2half_rn(s);
            }
            xr[30] = __float2half_rn(Ra[e]);
            xr[31] = __half(0.0f);
        }
    }
    __syncthreads();
    float acc[2][8][4];
    acc_zero(acc);
    mma_layer(sX, g_bRe0, 2, acc);
    __syncthreads();
    epi_x(sX, acc, b0);
    __syncthreads();
    acc_zero(acc);
    mma_layer(sX, g_bRe1, 8, acc);
    __syncthreads();
    epi_x(sX, acc, b1);
    __syncthreads();
    acc_zero(acc);
    mma_layer(sX, g_bRe2, 8, acc);
    __syncthreads();
    epi_x(sX, acc, b2);
    __syncthreads();
    copy_out(g_rel + (size_t)blockIdx.x * 16384, sX);
}

// ---------------- propagation edge pass ----------------
__global__ void __launch_bounds__(256, 2) k_prop(const int* __restrict__ recv,
                                                 const int* __restrict__ send,
                                                 const __half* __restrict__ eff,
                                                 const float* __restrict__ rp_b, int use_eff) {
    extern __shared__ __half sm_[];
    __half* sX = sm_;
    int e0 = blockIdx.x * 128;
    s_copy(sX, g_rel + (size_t)blockIdx.x * 16384);
    __syncthreads();
    float acc[2][8][4];
    acc_zero(acc);
    mma_layer(sX, g_bRp, 8, acc);
    if (use_eff) {
        __syncthreads();
        s_gather(sX, eff, recv, e0);
        __syncthreads();
        mma_layer(sX, g_bRp + 8 * CHUNKH, 8, acc);
        __syncthreads();
        s_gather(sX, eff, send, e0);
        __syncthreads();
        mma_layer(sX, g_bRp + 16 * CHUNKH, 8, acc);
    }
    epi_scatter(recv, e0, acc, rp_b);
}

// ---------------- particle update: [pe, agg] -> 128 ----------------
__global__ void __launch_bounds__(256, 2) k_pupdate(const float* __restrict__ pp_b,
                                                    __half* __restrict__ effOut) {
    extern __shared__ __half sm_[];
    __half* sX = sm_;
    s_copy(sX, g_pe + (size_t)blockIdx.x * 16384);
    __syncthreads();
    float acc[2][8][4];
    acc_zero(acc);
    mma_layer(sX, g_bPp, 8, acc);
    __syncthreads();
    s_copy_cvt(sX, g_agg + (size_t)blockIdx.x * 16384);
    __syncthreads();
    mma_layer(sX, g_bPp + 8 * CHUNKH, 8, acc);
    __syncthreads();
    epi_x(sX, acc, pp_b);
    __syncthreads();
    copy_out(effOut + (size_t)blockIdx.x * 16384, sX);
}

// ---------------- rigid pooling + small MLP + rigid output ----------------
__global__ void k_pool(const __half* __restrict__ eff) {
    int f = threadIdx.x;  // 128
    int r0 = blockIdx.x * 128;
    float s = 0.0f;
    for (int r = 0; r < 128; ++r) s += __half2float(eff[(size_t)(r0 + r) * 128 + f]);
    atomicAdd(&g_pooled[f], s);
}

__global__ void k_rigid_mlp(const float* __restrict__ w0, const float* __restrict__ b0,
                            const float* __restrict__ w1, const float* __restrict__ b1,
                            const float* __restrict__ w2, const float* __restrict__ b2) {
    __shared__ float pin[128], h0[128], h1[128], tt[7];
    int t = threadIdx.x;  // 128
    pin[t] = g_pooled[t] * (1.0f / RIGN);
    __syncthreads();
    float s = b0[t];
    for (int k = 0; k < 128; ++k) s = fmaf(w0[t * 128 + k], pin[k], s);
    h0[t] = fmaxf(s, 0.0f);
    __syncthreads();
    s = b1[t];
    for (int k = 0; k < 128; ++k) s = fmaf(w1[t * 128 + k], h0[k], s);
    h1[t] = fmaxf(s, 0.0f);
    __syncthreads();
    if (t < 7) {
        s = b2[t];
        for (int k = 0; k < 128; ++k) s = fmaf(w2[t * 128 + k], h1[k], s);
        tt[t] = s;
    }
    __syncthreads();
    if (t == 0) {
        float qw = tt[0], qx = tt[1], qy = tt[2], qz = tt[3];
        float inv = rsqrtf(qw * qw + qx * qx + qy * qy + qz * qz);
        qw *= inv; qx *= inv; qy *= inv; qz *= inv;
        g_Rmat[0] = 1.0f - 2.0f * (qy * qy + qz * qz);
        g_Rmat[1] = 2.0f * (qx * qy + qz * qw);
        g_Rmat[2] = 2.0f * (qx * qz - qy * qw);
        g_Rmat[3] = 2.0f * (qx * qy - qz * qw);
        g_Rmat[4] = 1.0f - 2.0f * (qx * qx + qz * qz);
        g_Rmat[5] = 2.0f * (qy * qz + qx * qw);
        g_Rmat[6] = 2.0f * (qx * qz + qy * qw);
        g_Rmat[7] = 2.0f * (qy * qz - qx * qw);
        g_Rmat[8] = 1.0f - 2.0f * (qx * qx + qy * qy);
        g_tb[0] = tt[4]; g_tb[1] = tt[5]; g_tb[2] = tt[6];
    }
}

__global__ void k_rigid_out(const float* __restrict__ state, float* __restrict__ out) {
    int i = blockIdx.x * 256 + threadIdx.x;
    if (i >= RIGN) return;
    float c0 = g_cent[0], c1 = g_cent[1], c2 = g_cent[2];
    float p0x = state[i * 6], p0y = state[i * 6 + 1], p0z = state[i * 6 + 2];
    float dx = p0x - c0, dy = p0y - c1, dz = p0z - c2;
    float p1x = dx * g_Rmat[0] + dy * g_Rmat[3] + dz * g_Rmat[6] + g_tb[0] + c0;
    float p1y = dx * g_Rmat[1] + dy * g_Rmat[4] + dz * g_Rmat[7] + g_tb[1] + c1;
    float p1z = dx * g_Rmat[2] + dy * g_Rmat[5] + dz * g_Rmat[8] + g_tb[2] + c2;
    out[i * 3] = (p1x - p0x) * DT_INV;
    out[i * 3 + 1] = (p1y - p0y) * DT_INV;
    out[i * 3 + 2] = (p1z - p0z) * DT_INV;
}

// ---------------- fluid predictor: 128 -> 128 -> 128 -> 3 ----------------
__global__ void __launch_bounds__(256, 2) k_fluid(const __half* __restrict__ eff,
                                                  const float* __restrict__ fb0,
                                                  const float* __restrict__ fb1,
                                                  const float* __restrict__ fw2,
                                                  const float* __restrict__ fb2,
                                                  float* __restrict__ out) {
    extern __shared__ __half sm_[];
    __half* sX = sm_;
    int t = threadIdx.x;
    s_copy(sX, eff + (size_t)(32 + blockIdx.x) * 16384);
    __syncthreads();
    float acc[2][8][4];
    acc_zero(acc);
    mma_layer(sX, g_bFl0, 8, acc);
    __syncthreads();
    epi_x(sX, acc, fb0);
    __syncthreads();
    acc_zero(acc);
    mma_layer(sX, g_bFl1, 8, acc);
    __syncthreads();
    epi_x(sX, acc, fb1);
    __syncthreads();
    {
        int row = t & 127, grp = t >> 7;
        int p = RIGN + blockIdx.x * 128 + row;
        const __half* xr = sX + row * PXH;
        for (int ch = grp; ch < 3; ch += 2) {
            float o = __ldg(fb2 + ch);
            const float* wr = fw2 + ch * 128;
            for (int k = 0; k < 128; ++k) o = fmaf(__ldg(wr + k), __half2float(xr[k]), o);
            out[(size_t)p * 3 + ch] = o;
        }
    }
}

// ---------------- launch ----------------
extern "C" void kernel_launch(void* const* d_in, const int* in_sizes, int n_in,
                              void* d_out, int out_size) {
    const float* state = (const float*)d_in[0];
    const float* attr = (const float*)d_in[1];
    const float* Ra = (const float*)d_in[2];
    const int* recv = (const int*)d_in[3];
    const int* send = (const int*)d_in[4];
    const float* pe_w0 = (const float*)d_in[5];
    const float* pe_b0 = (const float*)d_in[6];
    const float* pe_w1 = (const float*)d_in[7];
    const float* pe_b1 = (const float*)d_in[8];
    const float* re_w0 = (const float*)d_in[9];
    const float* re_b0 = (const float*)d_in[10];
    const float* re_w1 = (const float*)d_in[11];
    const float* re_b1 = (const float*)d_in[12];
    const float* re_w2 = (const float*)d_in[13];
    const float* re_b2 = (const float*)d_in[14];
    const float* rp_w = (const float*)d_in[15];
    const float* rp_b = (const float*)d_in[16];
    const float* pp_w = (const float*)d_in[17];
    const float* pp_b = (const float*)d_in[18];
    const float* rg_w0 = (const float*)d_in[19];
    const float* rg_b0 = (const float*)d_in[20];
    const float* rg_w1 = (const float*)d_in[21];
    const float* rg_b1 = (const float*)d_in[22];
    const float* rg_w2 = (const float*)d_in[23];
    const float* rg_b2 = (const float*)d_in[24];
    const float* fl_w0 = (const float*)d_in[25];
    const float* fl_b0 = (const float*)d_in[26];
    const float* fl_w1 = (const float*)d_in[27];
    const float* fl_b1 = (const float*)d_in[28];
    const float* fl_w2 = (const float*)d_in[29];
    const float* fl_b2 = (const float*)d_in[30];
    float* out = (float*)d_out;

    cudaFuncSetAttribute(k_pe, cudaFuncAttributeMaxDynamicSharedMemorySize, SMEMSZ);
    cudaFuncSetAttribute(k_rel, cudaFuncAttributeMaxDynamicSharedMemorySize, SMEMSZ);
    cudaFuncSetAttribute(k_prop, cudaFuncAttributeMaxDynamicSharedMemorySize, SMEMSZ);
    cudaFuncSetAttribute(k_pupdate, cudaFuncAttributeMaxDynamicSharedMemorySize, SMEMSZ);
    cudaFuncSetAttribute(k_fluid, cudaFuncAttributeMaxDynamicSharedMemorySize, SMEMSZ);

    float* aggp; float* pooledp; __half* eff1p; __half* eff2p;
    cudaGetSymbolAddress((void**)&aggp, g_agg);
    cudaGetSymbolAddress((void**)&pooledp, g_pooled);
    cudaGetSymbolAddress((void**)&eff1p, g_eff1);
    cudaGetSymbolAddress((void**)&eff2p, g_eff2);

    k_mkblob<<<84, 256>>>(pe_w0, pe_w1, re_w0, re_w1, re_w2, rp_w, pp_w, fl_w0, fl_w1);
    k_centroid<<<1, 256>>>(state);
    k_pe<<<NP / 128, 256, SMEMSZ>>>(state, attr, pe_b0, pe_b1);
    k_rel<<<NE / 128, 256, SMEMSZ>>>(state, attr, Ra, recv, send, re_b0, re_b1, re_b2);

    // propagation step 1 (effect == 0 -> rel chunk only)
    cudaMemsetAsync(aggp, 0, (size_t)NP * 128 * sizeof(float));
    k_prop<<<NE / 128, 256, SMEMSZ>>>(recv, send, eff1p, rp_b, 0);
    k_pupdate<<<NP / 128, 256, SMEMSZ>>>(pp_b, eff1p);

    // propagation step 2
    cudaMemsetAsync(aggp, 0, (size_t)NP * 128 * sizeof(float));
    k_prop<<<NE / 128, 256, SMEMSZ>>>(recv, send, eff1p, rp_b, 1);
    k_pupdate<<<NP / 128, 256, SMEMSZ>>>(pp_b, eff2p);

    // rigid branch
    cudaMemsetAsync(pooledp, 0, 128 * sizeof(float));
    k_pool<<<RIGN / 128, 128>>>(eff2p);
    k_rigid_mlp<<<1, 128>>>(rg_w0, rg_b0, rg_w1, rg_b1, rg_w2, rg_b2);
    k_rigid_out<<<RIGN / 256, 256>>>(state, out);

    // fluid branch
    k_fluid<<<(NP - RIGN) / 128, 256, SMEMSZ>>>(eff2p, fl_b0, fl_b1, fl_w2, fl_b2, out);
}